// round 6
// baseline (speedup 1.0000x reference)
#include <cuda_runtime.h>
#include <cuda_fp16.h>
#include <cstdint>

#define CH    512
#define NNODE 20
#define PSTR  66
#define BUFSZ (PSTR * PSTR * CH)
#define MAXROUND 19

#define TILE_BYTES 16384                 // 128 rows x 128B (64 fp16)
#define STAGE_BYTES (4 * TILE_BYTES)     // Ah, Al, Bh, Bl
#define CONV_SMEM (2 * STAGE_BYTES + 1024)

// ======================= helpers =======================
__device__ __forceinline__ uint32_t smem_u32(const void* p) {
    uint32_t a;
    asm("{ .reg .u64 t; cvta.to.shared.u64 t, %1; cvt.u32.u64 %0, t; }" : "=r"(a) : "l"(p));
    return a;
}
__device__ __forceinline__ void ldsm_x4(uint32_t* r, uint32_t addr) {
    asm volatile("ldmatrix.sync.aligned.m8n8.x4.shared.b16 {%0,%1,%2,%3}, [%4];"
        : "=r"(r[0]), "=r"(r[1]), "=r"(r[2]), "=r"(r[3]) : "r"(addr));
}
__device__ __forceinline__ void mma16816(float* d, const uint32_t* a, const uint32_t* b) {
    asm volatile("mma.sync.aligned.m16n8k16.row.col.f32.f16.f16.f32 "
        "{%0,%1,%2,%3}, {%4,%5,%6,%7}, {%8,%9}, {%0,%1,%2,%3};"
        : "+f"(d[0]), "+f"(d[1]), "+f"(d[2]), "+f"(d[3])
        : "r"(a[0]), "r"(a[1]), "r"(a[2]), "r"(a[3]), "r"(b[0]), "r"(b[1]));
}
__device__ __forceinline__ void cp_async16(uint32_t saddr, const void* gaddr) {
    asm volatile("cp.async.cg.shared.global [%0], [%1], 16;" :: "r"(saddr), "l"(gaddr) : "memory");
}
#define CP_COMMIT() asm volatile("cp.async.commit_group;" ::: "memory")
#define CP_WAIT0()  asm volatile("cp.async.wait_group 0;" ::: "memory")

__device__ __forceinline__ float sigm(float v) { return 1.0f / (1.0f + expf(-v)); }

// ======================= device globals =======================
__device__ float g_A[3][BUFSZ];
__device__ float g_rh[NNODE][BUFSZ];
__device__ float g_z[NNODE][BUFSZ];

// fp16 hi/lo pairs are the ONLY storage for h / chsum / rh-conv-input / vis / V1
__device__ __align__(16) __half g_visT16[2][BUFSZ];
__device__ __align__(16) __half g_V116[2][BUFSZ];
__device__ __align__(16) __half g_h16[NNODE][2][BUFSZ];
__device__ __align__(16) __half g_cs16[NNODE][2][BUFSZ];
__device__ __align__(16) __half g_rh16[NNODE][2][BUFSZ];

__device__ __align__(16) __half g_wtc[6][2][9][512][512];   // [w*2+half][split][tap][o][c]
__device__ __align__(16) __half g_mtc[2][512][512];         // mconv vis half [split][o][c]

__device__ float g_lb[NNODE][CH];
__device__ float g_wsum[3][9][CH * CH];
__device__ float g_bmap[3][NNODE][9 * CH];

__device__ int g_level[NNODE];
__device__ int g_nchild[NNODE];
__device__ int g_child[NNODE][NNODE];
__device__ int g_edgeP[NNODE];
__device__ int g_edgeC[NNODE];
__device__ int g_nedge;
__device__ int g_root;

// ======================= tree prep =======================
__global__ void k_prep(const int* adj) {
    for (int n = 0; n < NNODE; ++n) g_nchild[n] = 0;
    int ne = 0;
    for (int p = 0; p < NNODE; ++p)
        for (int c = 0; c < NNODE; ++c)
            if (adj[p * NNODE + c] > 0) {
                g_child[p][g_nchild[p]++] = c;
                g_edgeP[ne] = p; g_edgeC[ne] = c; ++ne;
            }
    g_nedge = ne;
    for (int n = 0; n < NNODE; ++n) g_level[n] = 0;
    for (int it = 0; it < NNODE; ++it)
        for (int p = 0; p < NNODE; ++p)
            if (g_nchild[p] > 0) {
                int m = 0;
                for (int i = 0; i < g_nchild[p]; ++i) {
                    int lv = g_level[g_child[p][i]];
                    if (lv > m) m = lv;
                }
                g_level[p] = m + 1;
            }
    for (int c = 0; c < NNODE; ++c) {
        int cs = 0;
        for (int p = 0; p < NNODE; ++p) cs += adj[p * NNODE + c];
        if (cs == 0) { g_root = c; break; }
    }
}

// ======================= zero borders of fp16 conv-input planes =======================
__device__ __forceinline__ __half* hplane(int i) {
    if (i < 2) return g_visT16[i];
    if (i < 4) return g_V116[i - 2];
    i -= 4;
    if (i < 40) return g_h16[i >> 1][i & 1];
    i -= 40;
    if (i < 40) return g_cs16[i >> 1][i & 1];
    i -= 40;
    return g_rh16[i >> 1][i & 1];
}
__global__ void k_zero() {
    __half* p = hplane(blockIdx.y);
    int i = blockIdx.x * 256 + threadIdx.x;           // 260 border px * 512 ch
    int c = i & 511; int bi = i >> 9;
    int pp;
    if (bi < 66) pp = bi;
    else if (bi < 132) pp = 65 * PSTR + (bi - 66);
    else { int j = bi - 132; int y = 1 + (j >> 1); int x = (j & 1) * 65; pp = y * PSTR + x; }
    p[(size_t)pp * 512 + c] = __float2half(0.0f);
}

// ======================= vis NCHW -> padded NHWC fp16 hi/lo =======================
__global__ __launch_bounds__(256) void k_tvis(const float* vis) {
    __shared__ float sm[64][129];
    int y = blockIdx.x; int cc = blockIdx.y;
    for (int i = threadIdx.x; i < 64 * 128; i += 256) {
        int c = i >> 6, x = i & 63;
        sm[x][c] = vis[(size_t)(cc * 128 + c) * 4096 + y * 64 + x];
    }
    __syncthreads();
    for (int i = threadIdx.x; i < 64 * 128; i += 256) {
        int x = i >> 7, c = i & 127;
        float v = sm[x][c];
        size_t idx = (size_t)((y + 1) * PSTR + x + 1) * 512 + cc * 128 + c;
        __half hh = __float2half_rn(v);
        g_visT16[0][idx] = hh;
        g_visT16[1][idx] = __float2half_rn(v - __half2float(hh));
    }
}

// ======================= weight packing (fp16 hi/lo, [t][o][c]) =======================
__global__ void k_packtc(const float* rw, const float* uw, const float* ow, const float* mw) {
    size_t idx = (size_t)blockIdx.x * 256 + threadIdx.x;
    const size_t tot = (size_t)6 * 9 * 512 * 512;
    if (idx < tot) {
        int c = idx & 511; size_t r = idx >> 9;
        int o = r & 511; r >>= 9;
        int t = (int)(r % 9); r /= 9;
        int wh = (int)r; int w = wh >> 1, half = wh & 1;
        const float* wp = (w == 0) ? rw : (w == 1) ? uw : ow;
        float v = wp[((size_t)o * 1024 + half * 512 + c) * 9 + t];
        __half hi = __float2half_rn(v);
        float lo = v - __half2float(hi);
        g_wtc[wh][0][t][o][c] = hi;
        g_wtc[wh][1][t][o][c] = __float2half_rn(lo);
    } else if (idx < tot + (size_t)512 * 512) {
        size_t j = idx - tot; int c = (int)(j & 511); int o = (int)(j >> 9);
        float v = mw[(size_t)o * 812 + c];
        __half hi = __float2half_rn(v);
        float lo = v - __half2float(hi);
        g_mtc[0][o][c] = hi;
        g_mtc[1][o][c] = __float2half_rn(lo);
    }
}

// ======================= lb / wsum / bmap =======================
__global__ void k_lb(const float* lang, const float* mw, const float* mb) {
    int n = blockIdx.x; int c = threadIdx.x;
    float acc = mb[c];
    const float* wrow = mw + (size_t)c * 812 + 512;
    const float* lrow = lang + n * 300;
    for (int cl = 0; cl < 300; ++cl) acc += wrow[cl] * lrow[cl];
    g_lb[n][c] = acc;
}

__global__ void k_wsum(const float* rw, const float* uw, const float* ow) {
    int idx = blockIdx.x * 256 + threadIdx.x;
    int o = idx & 511; int c = (idx >> 9) & 511; int w = idx >> 18;
    const float* wp = (w == 0) ? rw : (w == 1) ? uw : ow;
    float t[9];
    const float* base = wp + ((size_t)o * 1024 + c) * 9;
#pragma unroll
    for (int k = 0; k < 9; ++k) t[k] = base[k];
#pragma unroll
    for (int cls = 0; cls < 9; ++cls) {
        int yt = cls / 3, xt = cls % 3;
        int kh0 = (yt == 0) ? 1 : 0, kh1 = (yt == 2) ? 1 : 2;
        int kw0 = (xt == 0) ? 1 : 0, kw1 = (xt == 2) ? 1 : 2;
        float s = 0.0f;
        for (int kh = kh0; kh <= kh1; ++kh)
            for (int kw = kw0; kw <= kw1; ++kw) s += t[kh * 3 + kw];
        g_wsum[w][cls][(size_t)c * CH + o] = s;
    }
}

__global__ __launch_bounds__(256) void k_bmap(const float* rb, const float* ub, const float* ob) {
    __shared__ float lb_s[NNODE * CH];
    int tid = threadIdx.x;
    int o = blockIdx.x * 256 + tid;
    int w = blockIdx.y / 9;
    int cls = blockIdx.y % 9;
    const float* lbf = &g_lb[0][0];
    for (int j = tid; j < NNODE * CH; j += 256) lb_s[j] = lbf[j];
    __syncthreads();
    const float* bptr = (w == 0) ? rb : (w == 1) ? ub : ob;
    float acc[NNODE];
    float bv = bptr[o];
#pragma unroll
    for (int n = 0; n < NNODE; ++n) acc[n] = bv;
    const float* ws = g_wsum[w][cls];
    for (int c = 0; c < CH; ++c) {
        float wv = ws[(size_t)c * CH + o];
#pragma unroll
        for (int n = 0; n < NNODE; ++n) acc[n] += lb_s[n * CH + c] * wv;
    }
#pragma unroll
    for (int n = 0; n < NNODE; ++n) g_bmap[w][n][cls * CH + o] = acc[n];
}

// ======================= stage loader (all cp.async, fp16 sources) =======================
__device__ __forceinline__ void load_stage(
    int tid, uint32_t sbase, int s, int q, int mode,
    const __half* wA0, const __half* wA1,
    const __half* inH, const __half* inL,
    int coBase, int y0)
{
    int t = (mode == 4) ? 0 : (q >> 3);
    int c0 = (q & 7) << 6;
    int tb = (mode == 4) ? 4 : t;
    int dy = tb / 3, dx = tb % 3;
    uint32_t sb = sbase + s * STAGE_BYTES;
#pragma unroll
    for (int p = 0; p < 8; ++p) {
        int idx = (tid << 3) | p;
        int split = idx >> 10; int rem = idx & 1023;
        int o = rem >> 3; int kc = rem & 7;
        const __half* gsrc = (split ? wA1 : wA0) +
            (size_t)t * 262144 + (size_t)(coBase + o) * 512 + c0 + kc * 8;
        cp_async16(sb + split * TILE_BYTES + o * 128 + ((kc ^ (o & 7)) << 4), gsrc);
    }
#pragma unroll
    for (int p = 0; p < 8; ++p) {
        int idx = (tid << 3) | p;
        int split = idx >> 10; int rem = idx & 1023;
        int n = rem >> 3; int kc = rem & 7;
        int ry = n >> 6, x = n & 63;
        const __half* gsrc = (split ? inL : inH) +
            (size_t)((y0 + ry + dy) * PSTR + x + dx) * 512 + c0 + kc * 8;
        cp_async16(sb + (2 + split) * TILE_BYTES + n * 128 + ((kc ^ (n & 7)) << 4), gsrc);
    }
    CP_COMMIT();
}

// ======================= tensor-core conv (mma.sync, pure fp16 stream) =======================
// mode 4: V1 = mconv_vis(visT16) -> V116              (K=512, center tap)
// mode 0: g_A[bz] = conv3(V116, w[bz] first half)
// mode 12: bz<20: reset per edge -> atomic rh ; bz>=20: update -> z
// mode 3: output conv (B=rh16) -> h16
__global__ __launch_bounds__(256) void k_conv(int mode, int round) {
    int bz = blockIdx.z;
    const __half* inH; const __half* inL;
    const __half* wA0; const __half* wA1;
    int emode, node = -1, outsel = 0;

    if (mode == 4) {
        inH = g_visT16[0]; inL = g_visT16[1];
        wA0 = &g_mtc[0][0][0]; wA1 = &g_mtc[1][0][0]; emode = 4;
    } else if (mode == 0) {
        inH = g_V116[0]; inL = g_V116[1];
        int wh = bz * 2;
        wA0 = &g_wtc[wh][0][0][0][0]; wA1 = &g_wtc[wh][1][0][0][0];
        emode = 0; outsel = bz;
    } else if (mode == 12) {
        if (bz < NNODE) {
            if (bz >= g_nedge) return;
            node = g_edgeP[bz];
            if (g_level[node] != round) return;
            int child = g_edgeC[bz];
            inH = g_h16[child][0]; inL = g_h16[child][1];
            wA0 = &g_wtc[1][0][0][0][0]; wA1 = &g_wtc[1][1][0][0][0];
            emode = 1;
        } else {
            node = bz - NNODE;
            if (g_level[node] != round || g_nchild[node] == 0) return;
            inH = g_cs16[node][0]; inL = g_cs16[node][1];
            wA0 = &g_wtc[3][0][0][0][0]; wA1 = &g_wtc[3][1][0][0][0];
            emode = 2;
        }
    } else {
        node = bz;
        if (g_level[node] != round || g_nchild[node] == 0) return;
        inH = g_rh16[node][0]; inL = g_rh16[node][1];
        wA0 = &g_wtc[5][0][0][0][0]; wA1 = &g_wtc[5][1][0][0][0];
        emode = 3;
    }

    extern __shared__ char dsm[];
    uint32_t sraw = smem_u32(dsm);
    uint32_t sbase = (sraw + 1023u) & ~1023u;

    int tid = threadIdx.x;
    int lane = tid & 31, wid = tid >> 5;
    int wm = wid >> 2, wn = wid & 3;        // warp tile: M64 x N32
    int lr = lane & 7, lg = lane >> 3;

    int y0 = blockIdx.x * 2;
    int coBase = blockIdx.y * 128;
    int nch = (mode == 4) ? 8 : 72;

    float acc[4][4][4];
#pragma unroll
    for (int a = 0; a < 4; ++a)
#pragma unroll
        for (int b = 0; b < 4; ++b)
#pragma unroll
            for (int c = 0; c < 4; ++c) acc[a][b][c] = 0.0f;

    // prologue
    load_stage(tid, sbase, 0, 0, mode, wA0, wA1, inH, inL, coBase, y0);
    CP_WAIT0();
    __syncthreads();

    for (int q = 0; q < nch; ++q) {
        int s = q & 1;
        if (q + 1 < nch)
            load_stage(tid, sbase, s ^ 1, q + 1, mode, wA0, wA1, inH, inL, coBase, y0);

        uint32_t stAh = sbase + s * STAGE_BYTES;
        uint32_t stAl = stAh + TILE_BYTES;
        uint32_t stBh = stAh + 2 * TILE_BYTES;
        uint32_t stBl = stAh + 3 * TILE_BYTES;

#pragma unroll
        for (int ks = 0; ks < 4; ++ks) {
            int kc0 = ks * 2;
            uint32_t af[4][4], bhf[2][4], blf[2][4];
#pragma unroll
            for (int tm = 0; tm < 4; ++tm) {
                int row = wm * 64 + tm * 16 + lr + ((lg & 1) << 3);
                int ch = kc0 + (lg >> 1);
                ldsm_x4(af[tm], stAh + row * 128 + ((ch ^ (row & 7)) << 4));
            }
#pragma unroll
            for (int p = 0; p < 2; ++p) {
                int row = wn * 32 + p * 16 + lr + ((lg >> 1) << 3);
                int ch = kc0 + (lg & 1);
                uint32_t off = row * 128 + ((ch ^ (row & 7)) << 4);
                ldsm_x4(bhf[p], stBh + off);
                ldsm_x4(blf[p], stBl + off);
            }
#pragma unroll
            for (int tm = 0; tm < 4; ++tm)
#pragma unroll
                for (int tn = 0; tn < 4; ++tn) {
                    mma16816(acc[tm][tn], af[tm], &bhf[tn >> 1][(tn & 1) * 2]);
                    mma16816(acc[tm][tn], af[tm], &blf[tn >> 1][(tn & 1) * 2]);
                }
#pragma unroll
            for (int tm = 0; tm < 4; ++tm) {
                int row = wm * 64 + tm * 16 + lr + ((lg & 1) << 3);
                int ch = kc0 + (lg >> 1);
                ldsm_x4(af[tm], stAl + row * 128 + ((ch ^ (row & 7)) << 4));
            }
#pragma unroll
            for (int tm = 0; tm < 4; ++tm)
#pragma unroll
                for (int tn = 0; tn < 4; ++tn)
                    mma16816(acc[tm][tn], af[tm], &bhf[tn >> 1][(tn & 1) * 2]);
        }
        CP_WAIT0();
        __syncthreads();
    }

    // ---------- epilogue ----------
#pragma unroll
    for (int tm = 0; tm < 4; ++tm) {
#pragma unroll
        for (int tn = 0; tn < 4; ++tn) {
#pragma unroll
            for (int j = 0; j < 4; ++j) {
                int m = wm * 64 + tm * 16 + (lane >> 2) + ((j >> 1) << 3);
                int n = wn * 32 + tn * 8 + ((lane & 3) << 1) + (j & 1);
                int o = coBase + m;
                int ry = n >> 6, x = n & 63;
                int y = y0 + ry;
                size_t pidx = (size_t)((y + 1) * PSTR + x + 1) * 512 + o;
                float v = acc[tm][tn][j];
                if (emode == 4) {
                    __half hh = __float2half_rn(v);
                    g_V116[0][pidx] = hh;
                    g_V116[1][pidx] = __float2half_rn(v - __half2float(hh));
                } else if (emode == 0) {
                    g_A[outsel][pidx] = v;
                } else {
                    int yt = (y == 0) ? 0 : ((y == 63) ? 2 : 1);
                    int xt = (x == 0) ? 0 : ((x == 63) ? 2 : 1);
                    int cls = yt * 3 + xt;
                    if (emode == 1) {
                        float r = sigm(v + g_A[0][pidx] + g_bmap[0][node][cls * CH + o]);
                        float hval = __half2float(inH[pidx]) + __half2float(inL[pidx]);
                        atomicAdd(&g_rh[node][pidx], r * hval);
                    } else if (emode == 2) {
                        g_z[node][pidx] = sigm(v + g_A[1][pidx] + g_bmap[1][node][cls * CH + o]);
                    } else {
                        float ri = tanhf(v + g_A[2][pidx] + g_bmap[2][node][cls * CH + o]);
                        float zz = g_z[node][pidx];
                        float cs = __half2float(g_cs16[node][0][pidx]) +
                                   __half2float(g_cs16[node][1][pidx]);
                        float hv = (1.0f - zz) * ri + zz * cs;
                        __half hh = __float2half_rn(hv);
                        g_h16[node][0][pidx] = hh;
                        g_h16[node][1][pidx] = __float2half_rn(hv - __half2float(hh));
                    }
                }
            }
        }
    }
}

// ======================= ch_sum (fp16 hi/lo) + zero rh =======================
__global__ void k_chsum(int round) {
    int n = blockIdx.y;
    if (g_level[n] != round || g_nchild[n] == 0) return;
    int nc = g_nchild[n];
    size_t base = (size_t)blockIdx.x * 2048 + threadIdx.x;
#pragma unroll
    for (int e = 0; e < 8; ++e) {
        size_t i = base + (size_t)e * 256;
        float s = 0.0f;
        for (int ci = 0; ci < nc; ++ci) {
            int c = g_child[n][ci];
            s += __half2float(g_h16[c][0][i]) + __half2float(g_h16[c][1][i]);
        }
        __half hh = __float2half_rn(s);
        g_cs16[n][0][i] = hh;
        g_cs16[n][1][i] = __float2half_rn(s - __half2float(hh));
        g_rh[n][i] = 0.0f;
    }
}

// ======================= rh -> fp16 hi/lo (per round, active nodes) =======================
__global__ void k_cvtrh(int round) {
    int n = blockIdx.y;
    if (g_level[n] != round || g_nchild[n] == 0) return;
    size_t base = (size_t)blockIdx.x * 2048 + threadIdx.x;
#pragma unroll
    for (int e = 0; e < 8; ++e) {
        size_t i = base + (size_t)e * 256;
        float v = g_rh[n][i];
        __half hh = __float2half_rn(v);
        g_rh16[n][0][i] = hh;
        g_rh16[n][1][i] = __float2half_rn(v - __half2float(hh));
    }
}

// ======================= leaves =======================
__global__ void k_leaf() {
    int n = blockIdx.y;
    if (g_nchild[n] != 0) return;
    size_t base = (size_t)blockIdx.x * 2048 + threadIdx.x;
#pragma unroll
    for (int e = 0; e < 8; ++e) {
        size_t i = base + (size_t)e * 256;
        int c = (int)(i & 511);
        int pp = (int)(i >> 9);
        int y = pp / PSTR - 1, x = pp % PSTR - 1;
        float hv = 0.0f;
        if ((unsigned)y < 64u && (unsigned)x < 64u) {
            int yt = (y == 0) ? 0 : ((y == 63) ? 2 : 1);
            int xt = (x == 0) ? 0 : ((x == 63) ? 2 : 1);
            int cls = yt * 3 + xt;
            float zu = sigm(g_A[1][i] + g_bmap[1][n][cls * CH + c]);
            float ro = tanhf(g_A[2][i] + g_bmap[2][n][cls * CH + c]);
            hv = (1.0f - zu) * ro;
        }
        __half hh = __float2half_rn(hv);
        g_h16[n][0][i] = hh;
        g_h16[n][1][i] = __float2half_rn(hv - __half2float(hh));
    }
}

// ======================= output: padded NHWC fp16 hi/lo -> NCHW fp32 =======================
__global__ __launch_bounds__(256) void k_copyout(float* out) {
    __shared__ float sm[64][129];
    int root = g_root;
    int y = blockIdx.x; int oc = blockIdx.y;
    const __half* srcH = g_h16[root][0] + (size_t)((y + 1) * PSTR + 1) * 512 + oc * 128;
    const __half* srcL = g_h16[root][1] + (size_t)((y + 1) * PSTR + 1) * 512 + oc * 128;
    for (int i = threadIdx.x; i < 64 * 128; i += 256) {
        int x = i >> 7, o = i & 127;
        sm[x][o] = __half2float(srcH[(size_t)x * 512 + o]) +
                   __half2float(srcL[(size_t)x * 512 + o]);
    }
    __syncthreads();
    for (int i = threadIdx.x; i < 64 * 128; i += 256) {
        int o = i >> 6, x = i & 63;
        out[(size_t)(oc * 128 + o) * 4096 + y * 64 + x] = sm[x][o];
    }
}

// ======================= launch =======================
extern "C" void kernel_launch(void* const* d_in, const int* in_sizes, int n_in,
                              void* d_out, int out_size) {
    const float* vis  = (const float*)d_in[0];
    const float* lang = (const float*)d_in[1];
    const int*   adj  = (const int*)d_in[2];
    const float* mw   = (const float*)d_in[3];
    const float* mb   = (const float*)d_in[4];
    const float* rw   = (const float*)d_in[5];
    const float* rb   = (const float*)d_in[6];
    const float* uw   = (const float*)d_in[7];
    const float* ub   = (const float*)d_in[8];
    const float* ow   = (const float*)d_in[9];
    const float* ob   = (const float*)d_in[10];
    float* out = (float*)d_out;

    cudaFuncSetAttribute(k_conv, cudaFuncAttributeMaxDynamicSharedMemorySize, CONV_SMEM);

    k_prep<<<1, 1>>>(adj);
    k_zero<<<dim3(520, 124), 256>>>();
    k_tvis<<<dim3(64, 4), 256>>>(vis);
    {
        size_t tot = (size_t)6 * 9 * 512 * 512 + (size_t)512 * 512;
        k_packtc<<<(unsigned)((tot + 255) / 256), 256>>>(rw, uw, ow, mw);
    }
    k_wsum<<<(3 * CH * CH) / 256, 256>>>(rw, uw, ow);
    k_lb<<<NNODE, CH>>>(lang, mw, mb);
    k_bmap<<<dim3(2, 27), 256>>>(rb, ub, ob);

    k_conv<<<dim3(32, 4, 1), 256, CONV_SMEM>>>(4, 0);   // V1 -> V116
    k_conv<<<dim3(32, 4, 3), 256, CONV_SMEM>>>(0, 0);   // A_r, A_u, A_o
    k_leaf<<<dim3(1089, NNODE), 256>>>();

    for (int t = 1; t <= MAXROUND; ++t) {
        k_chsum<<<dim3(1089, NNODE), 256>>>(t);
        k_conv<<<dim3(32, 4, 2 * NNODE), 256, CONV_SMEM>>>(12, t);  // reset + update
        k_cvtrh<<<dim3(1089, NNODE), 256>>>(t);
        k_conv<<<dim3(32, 4, NNODE), 256, CONV_SMEM>>>(3, t);       // output
    }
    k_copyout<<<dim3(64, 4), 256>>>(out);
}

// round 8
// speedup vs baseline: 1.4526x; 1.4526x over previous
#include <cuda_runtime.h>
#include <cuda_fp16.h>
#include <cstdint>

#define CH    512
#define NNODE 20
#define PSTR  66
#define BUFSZ (PSTR * PSTR * CH)
#define MAXROUND 19

#define A_TILE  16384                    // per split: 128 rows x 128B
#define A_STAGE (2 * A_TILE)             // 32 KB (hi+lo)
#define B_ROWS  264                      // 4 padded rows x 66 cols
#define B_TILE  (B_ROWS * 128)           // 33792 B per split
#define B_STAGE (2 * B_TILE)             // 67584 B (hi+lo)
#define B_OFF   (2 * A_STAGE)            // B stages start after A stages
#define CONV_SMEM (2 * A_STAGE + 2 * B_STAGE + 1024)

// ======================= helpers =======================
__device__ __forceinline__ uint32_t smem_u32(const void* p) {
    uint32_t a;
    asm("{ .reg .u64 t; cvta.to.shared.u64 t, %1; cvt.u32.u64 %0, t; }" : "=r"(a) : "l"(p));
    return a;
}
__device__ __forceinline__ void ldsm_x4(uint32_t* r, uint32_t addr) {
    asm volatile("ldmatrix.sync.aligned.m8n8.x4.shared.b16 {%0,%1,%2,%3}, [%4];"
        : "=r"(r[0]), "=r"(r[1]), "=r"(r[2]), "=r"(r[3]) : "r"(addr));
}
__device__ __forceinline__ void mma16816(float* d, const uint32_t* a, const uint32_t* b) {
    asm volatile("mma.sync.aligned.m16n8k16.row.col.f32.f16.f16.f32 "
        "{%0,%1,%2,%3}, {%4,%5,%6,%7}, {%8,%9}, {%0,%1,%2,%3};"
        : "+f"(d[0]), "+f"(d[1]), "+f"(d[2]), "+f"(d[3])
        : "r"(a[0]), "r"(a[1]), "r"(a[2]), "r"(a[3]), "r"(b[0]), "r"(b[1]));
}
__device__ __forceinline__ void cp_async16(uint32_t saddr, const void* gaddr) {
    asm volatile("cp.async.cg.shared.global [%0], [%1], 16;" :: "r"(saddr), "l"(gaddr) : "memory");
}
#define CP_COMMIT() asm volatile("cp.async.commit_group;" ::: "memory")
#define CP_WAIT0()  asm volatile("cp.async.wait_group 0;" ::: "memory")

__device__ __forceinline__ float sigm(float v) { return 1.0f / (1.0f + expf(-v)); }

// ======================= device globals =======================
__device__ float g_A[3][BUFSZ];
__device__ float g_rh[NNODE][BUFSZ];
__device__ float g_z[NNODE][BUFSZ];

// fp16 hi/lo pairs are the ONLY storage for h / chsum / rh-conv-input / vis / V1
__device__ __align__(16) __half g_visT16[2][BUFSZ];
__device__ __align__(16) __half g_V116[2][BUFSZ];
__device__ __align__(16) __half g_h16[NNODE][2][BUFSZ];
__device__ __align__(16) __half g_cs16[NNODE][2][BUFSZ];
__device__ __align__(16) __half g_rh16[NNODE][2][BUFSZ];

__device__ __align__(16) __half g_wtc[6][2][9][512][512];   // [w*2+half][split][tap][o][c]
__device__ __align__(16) __half g_mtc[2][512][512];         // mconv vis half [split][o][c]

__device__ float g_lb[NNODE][CH];
__device__ float g_wsum[3][9][CH * CH];
__device__ float g_bmap[3][NNODE][9 * CH];

__device__ int g_level[NNODE];
__device__ int g_nchild[NNODE];
__device__ int g_child[NNODE][NNODE];
__device__ int g_edgeP[NNODE];
__device__ int g_edgeC[NNODE];
__device__ int g_nedge;
__device__ int g_root;

// ======================= tree prep =======================
__global__ void k_prep(const int* adj) {
    for (int n = 0; n < NNODE; ++n) g_nchild[n] = 0;
    int ne = 0;
    for (int p = 0; p < NNODE; ++p)
        for (int c = 0; c < NNODE; ++c)
            if (adj[p * NNODE + c] > 0) {
                g_child[p][g_nchild[p]++] = c;
                g_edgeP[ne] = p; g_edgeC[ne] = c; ++ne;
            }
    g_nedge = ne;
    for (int n = 0; n < NNODE; ++n) g_level[n] = 0;
    for (int it = 0; it < NNODE; ++it)
        for (int p = 0; p < NNODE; ++p)
            if (g_nchild[p] > 0) {
                int m = 0;
                for (int i = 0; i < g_nchild[p]; ++i) {
                    int lv = g_level[g_child[p][i]];
                    if (lv > m) m = lv;
                }
                g_level[p] = m + 1;
            }
    for (int c = 0; c < NNODE; ++c) {
        int cs = 0;
        for (int p = 0; p < NNODE; ++p) cs += adj[p * NNODE + c];
        if (cs == 0) { g_root = c; break; }
    }
}

// ======================= zero borders of fp16 conv-input planes =======================
__device__ __forceinline__ __half* hplane(int i) {
    if (i < 2) return g_visT16[i];
    if (i < 4) return g_V116[i - 2];
    i -= 4;
    if (i < 40) return g_h16[i >> 1][i & 1];
    i -= 40;
    if (i < 40) return g_cs16[i >> 1][i & 1];
    i -= 40;
    return g_rh16[i >> 1][i & 1];
}
__global__ void k_zero() {
    __half* p = hplane(blockIdx.y);
    int i = blockIdx.x * 256 + threadIdx.x;           // 260 border px * 512 ch
    int c = i & 511; int bi = i >> 9;
    int pp;
    if (bi < 66) pp = bi;
    else if (bi < 132) pp = 65 * PSTR + (bi - 66);
    else { int j = bi - 132; int y = 1 + (j >> 1); int x = (j & 1) * 65; pp = y * PSTR + x; }
    p[(size_t)pp * 512 + c] = __float2half(0.0f);
}

// ======================= vis NCHW -> padded NHWC fp16 hi/lo =======================
__global__ __launch_bounds__(256) void k_tvis(const float* vis) {
    __shared__ float sm[64][129];
    int y = blockIdx.x; int cc = blockIdx.y;
    for (int i = threadIdx.x; i < 64 * 128; i += 256) {
        int c = i >> 6, x = i & 63;
        sm[x][c] = vis[(size_t)(cc * 128 + c) * 4096 + y * 64 + x];
    }
    __syncthreads();
    for (int i = threadIdx.x; i < 64 * 128; i += 256) {
        int x = i >> 7, c = i & 127;
        float v = sm[x][c];
        size_t idx = (size_t)((y + 1) * PSTR + x + 1) * 512 + cc * 128 + c;
        __half hh = __float2half_rn(v);
        g_visT16[0][idx] = hh;
        g_visT16[1][idx] = __float2half_rn(v - __half2float(hh));
    }
}

// ======================= weight packing (fp16 hi/lo, [t][o][c]) =======================
__global__ void k_packtc(const float* rw, const float* uw, const float* ow, const float* mw) {
    size_t idx = (size_t)blockIdx.x * 256 + threadIdx.x;
    const size_t tot = (size_t)6 * 9 * 512 * 512;
    if (idx < tot) {
        int c = idx & 511; size_t r = idx >> 9;
        int o = r & 511; r >>= 9;
        int t = (int)(r % 9); r /= 9;
        int wh = (int)r; int w = wh >> 1, half = wh & 1;
        const float* wp = (w == 0) ? rw : (w == 1) ? uw : ow;
        float v = wp[((size_t)o * 1024 + half * 512 + c) * 9 + t];
        __half hi = __float2half_rn(v);
        float lo = v - __half2float(hi);
        g_wtc[wh][0][t][o][c] = hi;
        g_wtc[wh][1][t][o][c] = __float2half_rn(lo);
    } else if (idx < tot + (size_t)512 * 512) {
        size_t j = idx - tot; int c = (int)(j & 511); int o = (int)(j >> 9);
        float v = mw[(size_t)o * 812 + c];
        __half hi = __float2half_rn(v);
        float lo = v - __half2float(hi);
        g_mtc[0][o][c] = hi;
        g_mtc[1][o][c] = __float2half_rn(lo);
    }
}

// ======================= lb / wsum / bmap =======================
__global__ void k_lb(const float* lang, const float* mw, const float* mb) {
    int n = blockIdx.x; int c = threadIdx.x;
    float acc = mb[c];
    const float* wrow = mw + (size_t)c * 812 + 512;
    const float* lrow = lang + n * 300;
    for (int cl = 0; cl < 300; ++cl) acc += wrow[cl] * lrow[cl];
    g_lb[n][c] = acc;
}

__global__ void k_wsum(const float* rw, const float* uw, const float* ow) {
    int idx = blockIdx.x * 256 + threadIdx.x;
    int o = idx & 511; int c = (idx >> 9) & 511; int w = idx >> 18;
    const float* wp = (w == 0) ? rw : (w == 1) ? uw : ow;
    float t[9];
    const float* base = wp + ((size_t)o * 1024 + c) * 9;
#pragma unroll
    for (int k = 0; k < 9; ++k) t[k] = base[k];
#pragma unroll
    for (int cls = 0; cls < 9; ++cls) {
        int yt = cls / 3, xt = cls % 3;
        int kh0 = (yt == 0) ? 1 : 0, kh1 = (yt == 2) ? 1 : 2;
        int kw0 = (xt == 0) ? 1 : 0, kw1 = (xt == 2) ? 1 : 2;
        float s = 0.0f;
        for (int kh = kh0; kh <= kh1; ++kh)
            for (int kw = kw0; kw <= kw1; ++kw) s += t[kh * 3 + kw];
        g_wsum[w][cls][(size_t)c * CH + o] = s;
    }
}

__global__ __launch_bounds__(256) void k_bmap(const float* rb, const float* ub, const float* ob) {
    __shared__ float lb_s[NNODE * CH];
    int tid = threadIdx.x;
    int o = blockIdx.x * 256 + tid;
    int w = blockIdx.y / 9;
    int cls = blockIdx.y % 9;
    const float* lbf = &g_lb[0][0];
    for (int j = tid; j < NNODE * CH; j += 256) lb_s[j] = lbf[j];
    __syncthreads();
    const float* bptr = (w == 0) ? rb : (w == 1) ? ub : ob;
    float acc[NNODE];
    float bv = bptr[o];
#pragma unroll
    for (int n = 0; n < NNODE; ++n) acc[n] = bv;
    const float* ws = g_wsum[w][cls];
    for (int c = 0; c < CH; ++c) {
        float wv = ws[(size_t)c * CH + o];
#pragma unroll
        for (int n = 0; n < NNODE; ++n) acc[n] += lb_s[n * CH + c] * wv;
    }
#pragma unroll
    for (int n = 0; n < NNODE; ++n) g_bmap[w][n][cls * CH + o] = acc[n];
}

// ======================= A loader: one (weight-tap, c-chunk) weight tile =======================
// wt is the WEIGHT plane index (0 for mode 4 / mconv; tap index otherwise)
__device__ __forceinline__ void load_A(
    int tid, uint32_t abase,
    const __half* wA0, const __half* wA1,
    int wt, int c0, int coBase)
{
#pragma unroll
    for (int p = 0; p < 4; ++p) {
        int idx = tid * 4 + p;                 // 0..1023
        int o = idx >> 3; int kc = idx & 7;
        size_t goff = (size_t)wt * 262144 + (size_t)(coBase + o) * 512 + c0 + kc * 8;
        uint32_t so = (uint32_t)o * 128 + ((kc ^ (o & 7)) << 4);
        cp_async16(abase + so, wA0 + goff);
        cp_async16(abase + A_TILE + so, wA1 + goff);
    }
}

// ======================= B halo loader: quarter of a c-chunk halo =======================
// halo = padded rows [y0, y0+4) x cols [0, 66) for channels [c0, c0+64)
__device__ __forceinline__ void load_Bq(
    int tid, uint32_t bbase,
    const __half* inH, const __half* inL,
    int c0, int y0, int part)
{
#pragma unroll
    for (int it = 0; it < 3; ++it) {
        int idx0 = it * 256 + tid;
        if (idx0 < 528) {
            int idx = part * 528 + idx0;       // 0..2111
            int p = idx >> 3; int kc = idx & 7;
            int pr = p / 66, pc = p % 66;
            size_t goff = (size_t)((y0 + pr) * PSTR + pc) * 512 + c0 + kc * 8;
            uint32_t so = (uint32_t)p * 128 + ((kc ^ (p & 7)) << 4);
            cp_async16(bbase + so, inH + goff);
            cp_async16(bbase + B_TILE + so, inL + goff);
        }
    }
}

// ======================= tensor-core conv (tap-reuse B halo in smem) =======================
// mode 4: V1 = mconv_vis(visT16) -> V116              (K=512, center tap, weight plane 0)
// mode 0: g_A[bz] = conv3(V116, w[bz] first half)
// mode 12: bz<20: reset per edge -> atomic rh ; bz>=20: update -> z
// mode 3: output conv (B=rh16) -> h16
__global__ __launch_bounds__(256) void k_conv(int mode, int round) {
    int bz = blockIdx.z;
    const __half* inH; const __half* inL;
    const __half* wA0; const __half* wA1;
    int emode, node = -1, outsel = 0;

    if (mode == 4) {
        inH = g_visT16[0]; inL = g_visT16[1];
        wA0 = &g_mtc[0][0][0]; wA1 = &g_mtc[1][0][0]; emode = 4;
    } else if (mode == 0) {
        inH = g_V116[0]; inL = g_V116[1];
        int wh = bz * 2;
        wA0 = &g_wtc[wh][0][0][0][0]; wA1 = &g_wtc[wh][1][0][0][0];
        emode = 0; outsel = bz;
    } else if (mode == 12) {
        if (bz < NNODE) {
            if (bz >= g_nedge) return;
            node = g_edgeP[bz];
            if (g_level[node] != round) return;
            int child = g_edgeC[bz];
            inH = g_h16[child][0]; inL = g_h16[child][1];
            wA0 = &g_wtc[1][0][0][0][0]; wA1 = &g_wtc[1][1][0][0][0];
            emode = 1;
        } else {
            node = bz - NNODE;
            if (g_level[node] != round || g_nchild[node] == 0) return;
            inH = g_cs16[node][0]; inL = g_cs16[node][1];
            wA0 = &g_wtc[3][0][0][0][0]; wA1 = &g_wtc[3][1][0][0][0];
            emode = 2;
        }
    } else {
        node = bz;
        if (g_level[node] != round || g_nchild[node] == 0) return;
        inH = g_rh16[node][0]; inL = g_rh16[node][1];
        wA0 = &g_wtc[5][0][0][0][0]; wA1 = &g_wtc[5][1][0][0][0];
        emode = 3;
    }

    extern __shared__ char dsm[];
    uint32_t sraw = smem_u32(dsm);
    uint32_t sbase = (sraw + 1023u) & ~1023u;

    int tid = threadIdx.x;
    int lane = tid & 31, wid = tid >> 5;
    int wm = wid >> 2, wn = wid & 3;        // warp tile: M64 x N32
    int lr = lane & 7, lg = lane >> 3;

    int y0 = blockIdx.x * 2;
    int coBase = blockIdx.y * 128;
    int tap_lo = (mode == 4) ? 4 : 0;
    int tap_hi = (mode == 4) ? 4 : 8;

    // B-fragment pixel geometry (independent of tap): rows within the N=128 tile
    int nrow0 = wn * 32 + 0 * 16 + lr + ((lg >> 1) << 3);
    int nrow1 = wn * 32 + 1 * 16 + lr + ((lg >> 1) << 3);
    int ry0_ = nrow0 >> 6, xx0_ = nrow0 & 63;
    int ry1_ = nrow1 >> 6, xx1_ = nrow1 & 63;

    float acc[4][4][4];
#pragma unroll
    for (int a = 0; a < 4; ++a)
#pragma unroll
        for (int b = 0; b < 4; ++b)
#pragma unroll
            for (int c = 0; c < 4; ++c) acc[a][b][c] = 0.0f;

    // ---------- prologue: B halo chunk0 (all 4 parts) + A (chunk0, first tap) ----------
    {
        uint32_t b0 = sbase + B_OFF;
#pragma unroll
        for (int part = 0; part < 4; ++part)
            load_Bq(tid, b0, inH, inL, 0, y0, part);
        load_A(tid, sbase, wA0, wA1, (mode == 4) ? 0 : tap_lo, 0, coBase);
        CP_COMMIT();
        CP_WAIT0();
        __syncthreads();
    }

    int as = 0, bs = 0;
    for (int q = 0; q < 8; ++q) {
        int c0next = (q + 1) << 6;
        for (int tp = tap_lo; tp <= tap_hi; ++tp) {
            bool last = (q == 7) && (tp == tap_hi);
            if (!last) {
                int nq = q, nt = tp + 1;
                if (nt > tap_hi) { nq = q + 1; nt = tap_lo; }
                int wt = (mode == 4) ? 0 : nt;       // weight plane index
                load_A(tid, sbase + (as ^ 1) * A_STAGE, wA0, wA1, wt, nq << 6, coBase);
                if (q < 7) {
                    int part = tp - tap_lo;
                    uint32_t bn = sbase + B_OFF + (bs ^ 1) * B_STAGE;
                    if (mode == 4) {
#pragma unroll
                        for (int pp = 0; pp < 4; ++pp)
                            load_Bq(tid, bn, inH, inL, c0next, y0, pp);
                    } else if (part < 4) {
                        load_Bq(tid, bn, inH, inL, c0next, y0, part);
                    }
                }
                CP_COMMIT();
            }

            // ---- mma on A[as], B window of stage bs at tap tp ----
            {
                int dy = tp / 3, dx = tp % 3;
                int p0 = (ry0_ + dy) * 66 + xx0_ + dx;
                int p1 = (ry1_ + dy) * 66 + xx1_ + dx;
                uint32_t stA = sbase + as * A_STAGE;
                uint32_t stAl = stA + A_TILE;
                uint32_t stB = sbase + B_OFF + bs * B_STAGE;
                uint32_t stBl = stB + B_TILE;
                uint32_t rowoff0 = (uint32_t)p0 * 128;
                uint32_t rowoff1 = (uint32_t)p1 * 128;
                int sw0 = p0 & 7, sw1 = p1 & 7;

#pragma unroll
                for (int ks = 0; ks < 4; ++ks) {
                    int kc0 = ks * 2;
                    uint32_t af[4][4], bhf[2][4], blf[2][4];
#pragma unroll
                    for (int tm = 0; tm < 4; ++tm) {
                        int row = wm * 64 + tm * 16 + lr + ((lg & 1) << 3);
                        int ch = kc0 + (lg >> 1);
                        ldsm_x4(af[tm], stA + row * 128 + ((ch ^ (row & 7)) << 4));
                    }
                    {
                        int ch = kc0 + (lg & 1);
                        uint32_t o0 = rowoff0 + (uint32_t)((ch ^ sw0) << 4);
                        uint32_t o1 = rowoff1 + (uint32_t)((ch ^ sw1) << 4);
                        ldsm_x4(bhf[0], stB + o0);
                        ldsm_x4(bhf[1], stB + o1);
                        ldsm_x4(blf[0], stBl + o0);
                        ldsm_x4(blf[1], stBl + o1);
                    }
#pragma unroll
                    for (int tm = 0; tm < 4; ++tm)
#pragma unroll
                        for (int tn = 0; tn < 4; ++tn) {
                            mma16816(acc[tm][tn], af[tm], &bhf[tn >> 1][(tn & 1) * 2]);
                            mma16816(acc[tm][tn], af[tm], &blf[tn >> 1][(tn & 1) * 2]);
                        }
#pragma unroll
                    for (int tm = 0; tm < 4; ++tm) {
                        int row = wm * 64 + tm * 16 + lr + ((lg & 1) << 3);
                        int ch = kc0 + (lg >> 1);
                        ldsm_x4(af[tm], stAl + row * 128 + ((ch ^ (row & 7)) << 4));
                    }
#pragma unroll
                    for (int tm = 0; tm < 4; ++tm)
#pragma unroll
                        for (int tn = 0; tn < 4; ++tn)
                            mma16816(acc[tm][tn], af[tm], &bhf[tn >> 1][(tn & 1) * 2]);
                }
            }

            if (!last) CP_WAIT0();
            __syncthreads();
            as ^= 1;
        }
        bs ^= 1;
    }

    // ---------- epilogue ----------
#pragma unroll
    for (int tm = 0; tm < 4; ++tm) {
#pragma unroll
        for (int tn = 0; tn < 4; ++tn) {
#pragma unroll
            for (int j = 0; j < 4; ++j) {
                int m = wm * 64 + tm * 16 + (lane >> 2) + ((j >> 1) << 3);
                int n = wn * 32 + tn * 8 + ((lane & 3) << 1) + (j & 1);
                int o = coBase + m;
                int ry = n >> 6, x = n & 63;
                int y = y0 + ry;
                size_t pidx = (size_t)((y + 1) * PSTR + x + 1) * 512 + o;
                float v = acc[tm][tn][j];
                if (emode == 4) {
                    __half hh = __float2half_rn(v);
                    g_V116[0][pidx] = hh;
                    g_V116[1][pidx] = __float2half_rn(v - __half2float(hh));
                } else if (emode == 0) {
                    g_A[outsel][pidx] = v;
                } else {
                    int yt = (y == 0) ? 0 : ((y == 63) ? 2 : 1);
                    int xt = (x == 0) ? 0 : ((x == 63) ? 2 : 1);
                    int cls = yt * 3 + xt;
                    if (emode == 1) {
                        float r = sigm(v + g_A[0][pidx] + g_bmap[0][node][cls * CH + o]);
                        float hval = __half2float(inH[pidx]) + __half2float(inL[pidx]);
                        atomicAdd(&g_rh[node][pidx], r * hval);
                    } else if (emode == 2) {
                        g_z[node][pidx] = sigm(v + g_A[1][pidx] + g_bmap[1][node][cls * CH + o]);
                    } else {
                        float ri = tanhf(v + g_A[2][pidx] + g_bmap[2][node][cls * CH + o]);
                        float zz = g_z[node][pidx];
                        float cs = __half2float(g_cs16[node][0][pidx]) +
                                   __half2float(g_cs16[node][1][pidx]);
                        float hv = (1.0f - zz) * ri + zz * cs;
                        __half hh = __float2half_rn(hv);
                        g_h16[node][0][pidx] = hh;
                        g_h16[node][1][pidx] = __float2half_rn(hv - __half2float(hh));
                    }
                }
            }
        }
    }
}

// ======================= ch_sum (fp16 hi/lo) + zero rh =======================
__global__ void k_chsum(int round) {
    int n = blockIdx.y;
    if (g_level[n] != round || g_nchild[n] == 0) return;
    int nc = g_nchild[n];
    size_t base = (size_t)blockIdx.x * 2048 + threadIdx.x;
#pragma unroll
    for (int e = 0; e < 8; ++e) {
        size_t i = base + (size_t)e * 256;
        float s = 0.0f;
        for (int ci = 0; ci < nc; ++ci) {
            int c = g_child[n][ci];
            s += __half2float(g_h16[c][0][i]) + __half2float(g_h16[c][1][i]);
        }
        __half hh = __float2half_rn(s);
        g_cs16[n][0][i] = hh;
        g_cs16[n][1][i] = __float2half_rn(s - __half2float(hh));
        g_rh[n][i] = 0.0f;
    }
}

// ======================= rh -> fp16 hi/lo (per round, active nodes) =======================
__global__ void k_cvtrh(int round) {
    int n = blockIdx.y;
    if (g_level[n] != round || g_nchild[n] == 0) return;
    size_t base = (size_t)blockIdx.x * 2048 + threadIdx.x;
#pragma unroll
    for (int e = 0; e < 8; ++e) {
        size_t i = base + (size_t)e * 256;
        float v = g_rh[n][i];
        __half hh = __float2half_rn(v);
        g_rh16[n][0][i] = hh;
        g_rh16[n][1][i] = __float2half_rn(v - __half2float(hh));
    }
}

// ======================= leaves =======================
__global__ void k_leaf() {
    int n = blockIdx.y;
    if (g_nchild[n] != 0) return;
    size_t base = (size_t)blockIdx.x * 2048 + threadIdx.x;
#pragma unroll
    for (int e = 0; e < 8; ++e) {
        size_t i = base + (size_t)e * 256;
        int c = (int)(i & 511);
        int pp = (int)(i >> 9);
        int y = pp / PSTR - 1, x = pp % PSTR - 1;
        float hv = 0.0f;
        if ((unsigned)y < 64u && (unsigned)x < 64u) {
            int yt = (y == 0) ? 0 : ((y == 63) ? 2 : 1);
            int xt = (x == 0) ? 0 : ((x == 63) ? 2 : 1);
            int cls = yt * 3 + xt;
            float zu = sigm(g_A[1][i] + g_bmap[1][n][cls * CH + c]);
            float ro = tanhf(g_A[2][i] + g_bmap[2][n][cls * CH + c]);
            hv = (1.0f - zu) * ro;
        }
        __half hh = __float2half_rn(hv);
        g_h16[n][0][i] = hh;
        g_h16[n][1][i] = __float2half_rn(hv - __half2float(hh));
    }
}

// ======================= output: padded NHWC fp16 hi/lo -> NCHW fp32 =======================
__global__ __launch_bounds__(256) void k_copyout(float* out) {
    __shared__ float sm[64][129];
    int root = g_root;
    int y = blockIdx.x; int oc = blockIdx.y;
    const __half* srcH = g_h16[root][0] + (size_t)((y + 1) * PSTR + 1) * 512 + oc * 128;
    const __half* srcL = g_h16[root][1] + (size_t)((y + 1) * PSTR + 1) * 512 + oc * 128;
    for (int i = threadIdx.x; i < 64 * 128; i += 256) {
        int x = i >> 7, o = i & 127;
        sm[x][o] = __half2float(srcH[(size_t)x * 512 + o]) +
                   __half2float(srcL[(size_t)x * 512 + o]);
    }
    __syncthreads();
    for (int i = threadIdx.x; i < 64 * 128; i += 256) {
        int o = i >> 6, x = i & 63;
        out[(size_t)(oc * 128 + o) * 4096 + y * 64 + x] = sm[x][o];
    }
}

// ======================= launch =======================
extern "C" void kernel_launch(void* const* d_in, const int* in_sizes, int n_in,
                              void* d_out, int out_size) {
    const float* vis  = (const float*)d_in[0];
    const float* lang = (const float*)d_in[1];
    const int*   adj  = (const int*)d_in[2];
    const float* mw   = (const float*)d_in[3];
    const float* mb   = (const float*)d_in[4];
    const float* rw   = (const float*)d_in[5];
    const float* rb   = (const float*)d_in[6];
    const float* uw   = (const float*)d_in[7];
    const float* ub   = (const float*)d_in[8];
    const float* ow   = (const float*)d_in[9];
    const float* ob   = (const float*)d_in[10];
    float* out = (float*)d_out;

    cudaFuncSetAttribute(k_conv, cudaFuncAttributeMaxDynamicSharedMemorySize, CONV_SMEM);

    k_prep<<<1, 1>>>(adj);
    k_zero<<<dim3(520, 124), 256>>>();
    k_tvis<<<dim3(64, 4), 256>>>(vis);
    {
        size_t tot = (size_t)6 * 9 * 512 * 512 + (size_t)512 * 512;
        k_packtc<<<(unsigned)((tot + 255) / 256), 256>>>(rw, uw, ow, mw);
    }
    k_wsum<<<(3 * CH * CH) / 256, 256>>>(rw, uw, ow);
    k_lb<<<NNODE, CH>>>(lang, mw, mb);
    k_bmap<<<dim3(2, 27), 256>>>(rb, ub, ob);

    k_conv<<<dim3(32, 4, 1), 256, CONV_SMEM>>>(4, 0);   // V1 -> V116
    k_conv<<<dim3(32, 4, 3), 256, CONV_SMEM>>>(0, 0);   // A_r, A_u, A_o
    k_leaf<<<dim3(1089, NNODE), 256>>>();

    for (int t = 1; t <= MAXROUND; ++t) {
        k_chsum<<<dim3(1089, NNODE), 256>>>(t);
        k_conv<<<dim3(32, 4, 2 * NNODE), 256, CONV_SMEM>>>(12, t);  // reset + update
        k_cvtrh<<<dim3(1089, NNODE), 256>>>(t);
        k_conv<<<dim3(32, 4, NNODE), 256, CONV_SMEM>>>(3, t);       // output
    }
    k_copyout<<<dim3(64, 4), 256>>>(out);
}

// round 9
// speedup vs baseline: 1.7815x; 1.2264x over previous
#include <cuda_runtime.h>
#include <cuda_fp16.h>
#include <cstdint>

#define CH    512
#define NNODE 20
#define PSTR  66
#define BUFSZ (PSTR * PSTR * CH)
#define MAXROUND 19

#define A_TILE  16384                    // per split: 128 rows x 128B
#define A_STAGE (2 * A_TILE)             // 32 KB (hi+lo)
#define B_ROWS  264                      // 4 padded rows x 66 cols
#define B_TILE  (B_ROWS * 128)           // 33792 B per split
#define B_STAGE (2 * B_TILE)             // 67584 B (hi+lo)
#define B_OFF   (2 * A_STAGE)            // B stages start after A stages
#define CONV_SMEM (2 * A_STAGE + 2 * B_STAGE + 1024)

// ======================= helpers =======================
__device__ __forceinline__ uint32_t smem_u32(const void* p) {
    uint32_t a;
    asm("{ .reg .u64 t; cvta.to.shared.u64 t, %1; cvt.u32.u64 %0, t; }" : "=r"(a) : "l"(p));
    return a;
}
__device__ __forceinline__ void ldsm_x4(uint32_t* r, uint32_t addr) {
    asm volatile("ldmatrix.sync.aligned.m8n8.x4.shared.b16 {%0,%1,%2,%3}, [%4];"
        : "=r"(r[0]), "=r"(r[1]), "=r"(r[2]), "=r"(r[3]) : "r"(addr));
}
__device__ __forceinline__ void mma16816(float* d, const uint32_t* a, const uint32_t* b) {
    asm volatile("mma.sync.aligned.m16n8k16.row.col.f32.f16.f16.f32 "
        "{%0,%1,%2,%3}, {%4,%5,%6,%7}, {%8,%9}, {%0,%1,%2,%3};"
        : "+f"(d[0]), "+f"(d[1]), "+f"(d[2]), "+f"(d[3])
        : "r"(a[0]), "r"(a[1]), "r"(a[2]), "r"(a[3]), "r"(b[0]), "r"(b[1]));
}
__device__ __forceinline__ void cp_async16(uint32_t saddr, const void* gaddr) {
    asm volatile("cp.async.cg.shared.global [%0], [%1], 16;" :: "r"(saddr), "l"(gaddr) : "memory");
}
#define CP_COMMIT() asm volatile("cp.async.commit_group;" ::: "memory")
#define CP_WAIT0()  asm volatile("cp.async.wait_group 0;" ::: "memory")

__device__ __forceinline__ float sigm(float v) { return 1.0f / (1.0f + expf(-v)); }

// ======================= device globals =======================
__device__ float g_A[3][BUFSZ];
__device__ float g_rh[NNODE][BUFSZ];
__device__ float g_z[NNODE][BUFSZ];

// fp16 hi/lo pairs are the ONLY storage for h / chsum / rh-conv-input / vis / V1
__device__ __align__(16) __half g_visT16[2][BUFSZ];
__device__ __align__(16) __half g_V116[2][BUFSZ];
__device__ __align__(16) __half g_h16[NNODE][2][BUFSZ];
__device__ __align__(16) __half g_cs16[NNODE][2][BUFSZ];
__device__ __align__(16) __half g_rh16[NNODE][2][BUFSZ];

__device__ __align__(16) __half g_wtc[6][2][9][512][512];   // [w*2+half][split][tap][o][c]
__device__ __align__(16) __half g_mtc[2][512][512];         // mconv vis half [split][o][c]

__device__ float g_lb[NNODE][CH];
__device__ float g_wsum[3][9][CH * CH];
__device__ float g_bmap[3][NNODE][9 * CH];

__device__ int g_level[NNODE];
__device__ int g_nchild[NNODE];
__device__ int g_child[NNODE][NNODE];
__device__ int g_edgeP[NNODE];
__device__ int g_edgeC[NNODE];
__device__ int g_nedge;
__device__ int g_root;

// ======================= tree prep =======================
__global__ void k_prep(const int* adj) {
    for (int n = 0; n < NNODE; ++n) g_nchild[n] = 0;
    int ne = 0;
    for (int p = 0; p < NNODE; ++p)
        for (int c = 0; c < NNODE; ++c)
            if (adj[p * NNODE + c] > 0) {
                g_child[p][g_nchild[p]++] = c;
                g_edgeP[ne] = p; g_edgeC[ne] = c; ++ne;
            }
    g_nedge = ne;
    for (int n = 0; n < NNODE; ++n) g_level[n] = 0;
    for (int it = 0; it < NNODE; ++it)
        for (int p = 0; p < NNODE; ++p)
            if (g_nchild[p] > 0) {
                int m = 0;
                for (int i = 0; i < g_nchild[p]; ++i) {
                    int lv = g_level[g_child[p][i]];
                    if (lv > m) m = lv;
                }
                g_level[p] = m + 1;
            }
    for (int c = 0; c < NNODE; ++c) {
        int cs = 0;
        for (int p = 0; p < NNODE; ++p) cs += adj[p * NNODE + c];
        if (cs == 0) { g_root = c; break; }
    }
}

// ======================= zero borders of fp16 conv-input planes =======================
__device__ __forceinline__ __half* hplane(int i) {
    if (i < 2) return g_visT16[i];
    if (i < 4) return g_V116[i - 2];
    i -= 4;
    if (i < 40) return g_h16[i >> 1][i & 1];
    i -= 40;
    if (i < 40) return g_cs16[i >> 1][i & 1];
    i -= 40;
    return g_rh16[i >> 1][i & 1];
}
__global__ void k_zero() {
    __half* p = hplane(blockIdx.y);
    int i = blockIdx.x * 256 + threadIdx.x;           // 260 border px * 512 ch
    int c = i & 511; int bi = i >> 9;
    int pp;
    if (bi < 66) pp = bi;
    else if (bi < 132) pp = 65 * PSTR + (bi - 66);
    else { int j = bi - 132; int y = 1 + (j >> 1); int x = (j & 1) * 65; pp = y * PSTR + x; }
    p[(size_t)pp * 512 + c] = __float2half(0.0f);
}

// ======================= vis NCHW -> padded NHWC fp16 hi/lo =======================
__global__ __launch_bounds__(256) void k_tvis(const float* vis) {
    __shared__ float sm[64][129];
    int y = blockIdx.x; int cc = blockIdx.y;
    for (int i = threadIdx.x; i < 64 * 128; i += 256) {
        int c = i >> 6, x = i & 63;
        sm[x][c] = vis[(size_t)(cc * 128 + c) * 4096 + y * 64 + x];
    }
    __syncthreads();
    for (int i = threadIdx.x; i < 64 * 128; i += 256) {
        int x = i >> 7, c = i & 127;
        float v = sm[x][c];
        size_t idx = (size_t)((y + 1) * PSTR + x + 1) * 512 + cc * 128 + c;
        __half hh = __float2half_rn(v);
        g_visT16[0][idx] = hh;
        g_visT16[1][idx] = __float2half_rn(v - __half2float(hh));
    }
}

// ======================= weight packing (fp16 hi/lo, [t][o][c]) =======================
__global__ void k_packtc(const float* rw, const float* uw, const float* ow, const float* mw) {
    size_t idx = (size_t)blockIdx.x * 256 + threadIdx.x;
    const size_t tot = (size_t)6 * 9 * 512 * 512;
    if (idx < tot) {
        int c = idx & 511; size_t r = idx >> 9;
        int o = r & 511; r >>= 9;
        int t = (int)(r % 9); r /= 9;
        int wh = (int)r; int w = wh >> 1, half = wh & 1;
        const float* wp = (w == 0) ? rw : (w == 1) ? uw : ow;
        float v = wp[((size_t)o * 1024 + half * 512 + c) * 9 + t];
        __half hi = __float2half_rn(v);
        float lo = v - __half2float(hi);
        g_wtc[wh][0][t][o][c] = hi;
        g_wtc[wh][1][t][o][c] = __float2half_rn(lo);
    } else if (idx < tot + (size_t)512 * 512) {
        size_t j = idx - tot; int c = (int)(j & 511); int o = (int)(j >> 9);
        float v = mw[(size_t)o * 812 + c];
        __half hi = __float2half_rn(v);
        float lo = v - __half2float(hi);
        g_mtc[0][o][c] = hi;
        g_mtc[1][o][c] = __float2half_rn(lo);
    }
}

// ======================= lb / wsum / bmap =======================
__global__ void k_lb(const float* lang, const float* mw, const float* mb) {
    int n = blockIdx.x; int c = threadIdx.x;
    float acc = mb[c];
    const float* wrow = mw + (size_t)c * 812 + 512;
    const float* lrow = lang + n * 300;
    for (int cl = 0; cl < 300; ++cl) acc += wrow[cl] * lrow[cl];
    g_lb[n][c] = acc;
}

__global__ void k_wsum(const float* rw, const float* uw, const float* ow) {
    int idx = blockIdx.x * 256 + threadIdx.x;
    int o = idx & 511; int c = (idx >> 9) & 511; int w = idx >> 18;
    const float* wp = (w == 0) ? rw : (w == 1) ? uw : ow;
    float t[9];
    const float* base = wp + ((size_t)o * 1024 + c) * 9;
#pragma unroll
    for (int k = 0; k < 9; ++k) t[k] = base[k];
#pragma unroll
    for (int cls = 0; cls < 9; ++cls) {
        int yt = cls / 3, xt = cls % 3;
        int kh0 = (yt == 0) ? 1 : 0, kh1 = (yt == 2) ? 1 : 2;
        int kw0 = (xt == 0) ? 1 : 0, kw1 = (xt == 2) ? 1 : 2;
        float s = 0.0f;
        for (int kh = kh0; kh <= kh1; ++kh)
            for (int kw = kw0; kw <= kw1; ++kw) s += t[kh * 3 + kw];
        g_wsum[w][cls][(size_t)c * CH + o] = s;
    }
}

__global__ __launch_bounds__(256) void k_bmap(const float* rb, const float* ub, const float* ob) {
    __shared__ float lb_s[NNODE * CH];
    int tid = threadIdx.x;
    int o = blockIdx.x * 256 + tid;
    int w = blockIdx.y / 9;
    int cls = blockIdx.y % 9;
    const float* lbf = &g_lb[0][0];
    for (int j = tid; j < NNODE * CH; j += 256) lb_s[j] = lbf[j];
    __syncthreads();
    const float* bptr = (w == 0) ? rb : (w == 1) ? ub : ob;
    float acc[NNODE];
    float bv = bptr[o];
#pragma unroll
    for (int n = 0; n < NNODE; ++n) acc[n] = bv;
    const float* ws = g_wsum[w][cls];
    for (int c = 0; c < CH; ++c) {
        float wv = ws[(size_t)c * CH + o];
#pragma unroll
        for (int n = 0; n < NNODE; ++n) acc[n] += lb_s[n * CH + c] * wv;
    }
#pragma unroll
    for (int n = 0; n < NNODE; ++n) g_bmap[w][n][cls * CH + o] = acc[n];
}

// ======================= A loader: one (weight-tap, c-chunk) weight tile =======================
// wt is the WEIGHT plane index (0 for mode 4 / mconv; tap index otherwise)
// both=0: load only the hi plane (2-product mode)
__device__ __forceinline__ void load_A(
    int tid, uint32_t abase,
    const __half* wA0, const __half* wA1,
    int wt, int c0, int coBase, int both)
{
#pragma unroll
    for (int p = 0; p < 4; ++p) {
        int idx = tid * 4 + p;                 // 0..1023
        int o = idx >> 3; int kc = idx & 7;
        size_t goff = (size_t)wt * 262144 + (size_t)(coBase + o) * 512 + c0 + kc * 8;
        uint32_t so = (uint32_t)o * 128 + ((kc ^ (o & 7)) << 4);
        cp_async16(abase + so, wA0 + goff);
        if (both) cp_async16(abase + A_TILE + so, wA1 + goff);
    }
}

// ======================= B halo loader: quarter of a c-chunk halo =======================
// halo = padded rows [y0, y0+4) x cols [0, 66) for channels [c0, c0+64)
__device__ __forceinline__ void load_Bq(
    int tid, uint32_t bbase,
    const __half* inH, const __half* inL,
    int c0, int y0, int part)
{
#pragma unroll
    for (int it = 0; it < 3; ++it) {
        int idx0 = it * 256 + tid;
        if (idx0 < 528) {
            int idx = part * 528 + idx0;       // 0..2111
            int p = idx >> 3; int kc = idx & 7;
            int pr = p / 66, pc = p % 66;
            size_t goff = (size_t)((y0 + pr) * PSTR + pc) * 512 + c0 + kc * 8;
            uint32_t so = (uint32_t)p * 128 + ((kc ^ (p & 7)) << 4);
            cp_async16(bbase + so, inH + goff);
            cp_async16(bbase + B_TILE + so, inL + goff);
        }
    }
}

// ======================= tensor-core conv (tap-reuse B halo in smem) =======================
// mode 4: V1 = mconv_vis(visT16) -> V116              (3-product, weight plane 0)
// mode 0: g_A[bz] = conv3(V116, w[bz] first half)     (3-product)
// mode 12: bz<20: reset per edge -> atomic rh ; bz>=20: update -> z   (2-product)
// mode 3: output conv (B=rh16) -> h16                                  (2-product)
__global__ __launch_bounds__(256) void k_conv(int mode, int round) {
    int bz = blockIdx.z;
    const __half* inH; const __half* inL;
    const __half* wA0; const __half* wA1;
    int emode, node = -1, outsel = 0;

    if (mode == 4) {
        inH = g_visT16[0]; inL = g_visT16[1];
        wA0 = &g_mtc[0][0][0]; wA1 = &g_mtc[1][0][0]; emode = 4;
    } else if (mode == 0) {
        inH = g_V116[0]; inL = g_V116[1];
        int wh = bz * 2;
        wA0 = &g_wtc[wh][0][0][0][0]; wA1 = &g_wtc[wh][1][0][0][0];
        emode = 0; outsel = bz;
    } else if (mode == 12) {
        if (bz < NNODE) {
            if (bz >= g_nedge) return;
            node = g_edgeP[bz];
            if (g_level[node] != round) return;
            int child = g_edgeC[bz];
            inH = g_h16[child][0]; inL = g_h16[child][1];
            wA0 = &g_wtc[1][0][0][0][0]; wA1 = &g_wtc[1][1][0][0][0];
            emode = 1;
        } else {
            node = bz - NNODE;
            if (g_level[node] != round || g_nchild[node] == 0) return;
            inH = g_cs16[node][0]; inL = g_cs16[node][1];
            wA0 = &g_wtc[3][0][0][0][0]; wA1 = &g_wtc[3][1][0][0][0];
            emode = 2;
        }
    } else {
        node = bz;
        if (g_level[node] != round || g_nchild[node] == 0) return;
        inH = g_rh16[node][0]; inL = g_rh16[node][1];
        wA0 = &g_wtc[5][0][0][0][0]; wA1 = &g_wtc[5][1][0][0][0];
        emode = 3;
    }

    // precompute fields keep the 3rd (A-lo) product; recurrence convs drop it
    const int third = (emode == 0 || emode == 4) ? 1 : 0;

    extern __shared__ char dsm[];
    uint32_t sraw = smem_u32(dsm);
    uint32_t sbase = (sraw + 1023u) & ~1023u;

    int tid = threadIdx.x;
    int lane = tid & 31, wid = tid >> 5;
    int wm = wid >> 2, wn = wid & 3;        // warp tile: M64 x N32
    int lr = lane & 7, lg = lane >> 3;

    int y0 = blockIdx.x * 2;
    int coBase = blockIdx.y * 128;
    int tap_lo = (mode == 4) ? 4 : 0;
    int tap_hi = (mode == 4) ? 4 : 8;

    // B-fragment pixel geometry (independent of tap)
    int nrow0 = wn * 32 + 0 * 16 + lr + ((lg >> 1) << 3);
    int nrow1 = wn * 32 + 1 * 16 + lr + ((lg >> 1) << 3);
    int ry0_ = nrow0 >> 6, xx0_ = nrow0 & 63;
    int ry1_ = nrow1 >> 6, xx1_ = nrow1 & 63;

    float acc[4][4][4];
#pragma unroll
    for (int a = 0; a < 4; ++a)
#pragma unroll
        for (int b = 0; b < 4; ++b)
#pragma unroll
            for (int c = 0; c < 4; ++c) acc[a][b][c] = 0.0f;

    // ---------- prologue ----------
    {
        uint32_t b0 = sbase + B_OFF;
#pragma unroll
        for (int part = 0; part < 4; ++part)
            load_Bq(tid, b0, inH, inL, 0, y0, part);
        load_A(tid, sbase, wA0, wA1, (mode == 4) ? 0 : tap_lo, 0, coBase, third);
        CP_COMMIT();
        CP_WAIT0();
        __syncthreads();
    }

    int as = 0, bs = 0;
    for (int q = 0; q < 8; ++q) {
        int c0next = (q + 1) << 6;
        for (int tp = tap_lo; tp <= tap_hi; ++tp) {
            bool last = (q == 7) && (tp == tap_hi);
            if (!last) {
                int nq = q, nt = tp + 1;
                if (nt > tap_hi) { nq = q + 1; nt = tap_lo; }
                int wt = (mode == 4) ? 0 : nt;       // weight plane index
                load_A(tid, sbase + (as ^ 1) * A_STAGE, wA0, wA1, wt, nq << 6, coBase, third);
                if (q < 7) {
                    int part = tp - tap_lo;
                    uint32_t bn = sbase + B_OFF + (bs ^ 1) * B_STAGE;
                    if (mode == 4) {
#pragma unroll
                        for (int pp = 0; pp < 4; ++pp)
                            load_Bq(tid, bn, inH, inL, c0next, y0, pp);
                    } else if (part < 4) {
                        load_Bq(tid, bn, inH, inL, c0next, y0, part);
                    }
                }
                CP_COMMIT();
            }

            // ---- mma on A[as], B window of stage bs at tap tp ----
            {
                int dy = tp / 3, dx = tp % 3;
                int p0 = (ry0_ + dy) * 66 + xx0_ + dx;
                int p1 = (ry1_ + dy) * 66 + xx1_ + dx;
                uint32_t stA = sbase + as * A_STAGE;
                uint32_t stAl = stA + A_TILE;
                uint32_t stB = sbase + B_OFF + bs * B_STAGE;
                uint32_t stBl = stB + B_TILE;
                uint32_t rowoff0 = (uint32_t)p0 * 128;
                uint32_t rowoff1 = (uint32_t)p1 * 128;
                int sw0 = p0 & 7, sw1 = p1 & 7;

#pragma unroll
                for (int ks = 0; ks < 4; ++ks) {
                    int kc0 = ks * 2;
                    uint32_t af[4][4], bhf[2][4], blf[2][4];
#pragma unroll
                    for (int tm = 0; tm < 4; ++tm) {
                        int row = wm * 64 + tm * 16 + lr + ((lg & 1) << 3);
                        int ch = kc0 + (lg >> 1);
                        ldsm_x4(af[tm], stA + row * 128 + ((ch ^ (row & 7)) << 4));
                    }
                    {
                        int ch = kc0 + (lg & 1);
                        uint32_t o0 = rowoff0 + (uint32_t)((ch ^ sw0) << 4);
                        uint32_t o1 = rowoff1 + (uint32_t)((ch ^ sw1) << 4);
                        ldsm_x4(bhf[0], stB + o0);
                        ldsm_x4(bhf[1], stB + o1);
                        ldsm_x4(blf[0], stBl + o0);
                        ldsm_x4(blf[1], stBl + o1);
                    }
#pragma unroll
                    for (int tm = 0; tm < 4; ++tm)
#pragma unroll
                        for (int tn = 0; tn < 4; ++tn) {
                            mma16816(acc[tm][tn], af[tm], &bhf[tn >> 1][(tn & 1) * 2]);
                            mma16816(acc[tm][tn], af[tm], &blf[tn >> 1][(tn & 1) * 2]);
                        }
                    if (third) {
#pragma unroll
                        for (int tm = 0; tm < 4; ++tm) {
                            int row = wm * 64 + tm * 16 + lr + ((lg & 1) << 3);
                            int ch = kc0 + (lg >> 1);
                            ldsm_x4(af[tm], stAl + row * 128 + ((ch ^ (row & 7)) << 4));
                        }
#pragma unroll
                        for (int tm = 0; tm < 4; ++tm)
#pragma unroll
                            for (int tn = 0; tn < 4; ++tn)
                                mma16816(acc[tm][tn], af[tm], &bhf[tn >> 1][(tn & 1) * 2]);
                    }
                }
            }

            if (!last) CP_WAIT0();
            __syncthreads();
            as ^= 1;
        }
        bs ^= 1;
    }

    // ---------- epilogue ----------
#pragma unroll
    for (int tm = 0; tm < 4; ++tm) {
#pragma unroll
        for (int tn = 0; tn < 4; ++tn) {
#pragma unroll
            for (int j = 0; j < 4; ++j) {
                int m = wm * 64 + tm * 16 + (lane >> 2) + ((j >> 1) << 3);
                int n = wn * 32 + tn * 8 + ((lane & 3) << 1) + (j & 1);
                int o = coBase + m;
                int ry = n >> 6, x = n & 63;
                int y = y0 + ry;
                size_t pidx = (size_t)((y + 1) * PSTR + x + 1) * 512 + o;
                float v = acc[tm][tn][j];
                if (emode == 4) {
                    __half hh = __float2half_rn(v);
                    g_V116[0][pidx] = hh;
                    g_V116[1][pidx] = __float2half_rn(v - __half2float(hh));
                } else if (emode == 0) {
                    g_A[outsel][pidx] = v;
                } else {
                    int yt = (y == 0) ? 0 : ((y == 63) ? 2 : 1);
                    int xt = (x == 0) ? 0 : ((x == 63) ? 2 : 1);
                    int cls = yt * 3 + xt;
                    if (emode == 1) {
                        float r = sigm(v + g_A[0][pidx] + g_bmap[0][node][cls * CH + o]);
                        float hval = __half2float(inH[pidx]) + __half2float(inL[pidx]);
                        atomicAdd(&g_rh[node][pidx], r * hval);
                    } else if (emode == 2) {
                        g_z[node][pidx] = sigm(v + g_A[1][pidx] + g_bmap[1][node][cls * CH + o]);
                    } else {
                        float ri = tanhf(v + g_A[2][pidx] + g_bmap[2][node][cls * CH + o]);
                        float zz = g_z[node][pidx];
                        float cs = __half2float(g_cs16[node][0][pidx]) +
                                   __half2float(g_cs16[node][1][pidx]);
                        float hv = (1.0f - zz) * ri + zz * cs;
                        __half hh = __float2half_rn(hv);
                        g_h16[node][0][pidx] = hh;
                        g_h16[node][1][pidx] = __float2half_rn(hv - __half2float(hh));
                    }
                }
            }
        }
    }
}

// ======================= ch_sum (fp16 hi/lo) + zero rh =======================
__global__ void k_chsum(int round) {
    int n = blockIdx.y;
    if (g_level[n] != round || g_nchild[n] == 0) return;
    int nc = g_nchild[n];
    size_t base = (size_t)blockIdx.x * 2048 + threadIdx.x;
#pragma unroll
    for (int e = 0; e < 8; ++e) {
        size_t i = base + (size_t)e * 256;
        float s = 0.0f;
        for (int ci = 0; ci < nc; ++ci) {
            int c = g_child[n][ci];
            s += __half2float(g_h16[c][0][i]) + __half2float(g_h16[c][1][i]);
        }
        __half hh = __float2half_rn(s);
        g_cs16[n][0][i] = hh;
        g_cs16[n][1][i] = __float2half_rn(s - __half2float(hh));
        g_rh[n][i] = 0.0f;
    }
}

// ======================= rh -> fp16 hi/lo (per round, active nodes) =======================
__global__ void k_cvtrh(int round) {
    int n = blockIdx.y;
    if (g_level[n] != round || g_nchild[n] == 0) return;
    size_t base = (size_t)blockIdx.x * 2048 + threadIdx.x;
#pragma unroll
    for (int e = 0; e < 8; ++e) {
        size_t i = base + (size_t)e * 256;
        float v = g_rh[n][i];
        __half hh = __float2half_rn(v);
        g_rh16[n][0][i] = hh;
        g_rh16[n][1][i] = __float2half_rn(v - __half2float(hh));
    }
}

// ======================= leaves =======================
__global__ void k_leaf() {
    int n = blockIdx.y;
    if (g_nchild[n] != 0) return;
    size_t base = (size_t)blockIdx.x * 2048 + threadIdx.x;
#pragma unroll
    for (int e = 0; e < 8; ++e) {
        size_t i = base + (size_t)e * 256;
        int c = (int)(i & 511);
        int pp = (int)(i >> 9);
        int y = pp / PSTR - 1, x = pp % PSTR - 1;
        float hv = 0.0f;
        if ((unsigned)y < 64u && (unsigned)x < 64u) {
            int yt = (y == 0) ? 0 : ((y == 63) ? 2 : 1);
            int xt = (x == 0) ? 0 : ((x == 63) ? 2 : 1);
            int cls = yt * 3 + xt;
            float zu = sigm(g_A[1][i] + g_bmap[1][n][cls * CH + c]);
            float ro = tanhf(g_A[2][i] + g_bmap[2][n][cls * CH + c]);
            hv = (1.0f - zu) * ro;
        }
        __half hh = __float2half_rn(hv);
        g_h16[n][0][i] = hh;
        g_h16[n][1][i] = __float2half_rn(hv - __half2float(hh));
    }
}

// ======================= output: padded NHWC fp16 hi/lo -> NCHW fp32 =======================
__global__ __launch_bounds__(256) void k_copyout(float* out) {
    __shared__ float sm[64][129];
    int root = g_root;
    int y = blockIdx.x; int oc = blockIdx.y;
    const __half* srcH = g_h16[root][0] + (size_t)((y + 1) * PSTR + 1) * 512 + oc * 128;
    const __half* srcL = g_h16[root][1] + (size_t)((y + 1) * PSTR + 1) * 512 + oc * 128;
    for (int i = threadIdx.x; i < 64 * 128; i += 256) {
        int x = i >> 7, o = i & 127;
        sm[x][o] = __half2float(srcH[(size_t)x * 512 + o]) +
                   __half2float(srcL[(size_t)x * 512 + o]);
    }
    __syncthreads();
    for (int i = threadIdx.x; i < 64 * 128; i += 256) {
        int o = i >> 6, x = i & 63;
        out[(size_t)(oc * 128 + o) * 4096 + y * 64 + x] = sm[x][o];
    }
}

// ======================= launch =======================
extern "C" void kernel_launch(void* const* d_in, const int* in_sizes, int n_in,
                              void* d_out, int out_size) {
    const float* vis  = (const float*)d_in[0];
    const float* lang = (const float*)d_in[1];
    const int*   adj  = (const int*)d_in[2];
    const float* mw   = (const float*)d_in[3];
    const float* mb   = (const float*)d_in[4];
    const float* rw   = (const float*)d_in[5];
    const float* rb   = (const float*)d_in[6];
    const float* uw   = (const float*)d_in[7];
    const float* ub   = (const float*)d_in[8];
    const float* ow   = (const float*)d_in[9];
    const float* ob   = (const float*)d_in[10];
    float* out = (float*)d_out;

    cudaFuncSetAttribute(k_conv, cudaFuncAttributeMaxDynamicSharedMemorySize, CONV_SMEM);

    k_prep<<<1, 1>>>(adj);
    k_zero<<<dim3(520, 124), 256>>>();
    k_tvis<<<dim3(64, 4), 256>>>(vis);
    {
        size_t tot = (size_t)6 * 9 * 512 * 512 + (size_t)512 * 512;
        k_packtc<<<(unsigned)((tot + 255) / 256), 256>>>(rw, uw, ow, mw);
    }
    k_wsum<<<(3 * CH * CH) / 256, 256>>>(rw, uw, ow);
    k_lb<<<NNODE, CH>>>(lang, mw, mb);
    k_bmap<<<dim3(2, 27), 256>>>(rb, ub, ob);

    k_conv<<<dim3(32, 4, 1), 256, CONV_SMEM>>>(4, 0);   // V1 -> V116 (3-product)
    k_conv<<<dim3(32, 4, 3), 256, CONV_SMEM>>>(0, 0);   // A_r, A_u, A_o (3-product)
    k_leaf<<<dim3(1089, NNODE), 256>>>();

    for (int t = 1; t <= MAXROUND; ++t) {
        k_chsum<<<dim3(1089, NNODE), 256>>>(t);
        k_conv<<<dim3(32, 4, 2 * NNODE), 256, CONV_SMEM>>>(12, t);  // reset + update (2-product)
        k_cvtrh<<<dim3(1089, NNODE), 256>>>(t);
        k_conv<<<dim3(32, 4, NNODE), 256, CONV_SMEM>>>(3, t);       // output (2-product)
    }
    k_copyout<<<dim3(64, 4), 256>>>(out);
}

// round 11
// speedup vs baseline: 2.3161x; 1.3001x over previous
#include <cuda_runtime.h>
#include <cuda_fp16.h>
#include <cstdint>

#define CH    512
#define NNODE 20
#define PSTR  66
#define BUFSZ (PSTR * PSTR * CH)
#define MAXROUND 19

#define A_TILE  16384                    // per split: 128 rows x 128B
#define A_STAGE (2 * A_TILE)             // 32 KB (hi+lo)
#define B_ROWS  264                      // 4 padded rows x 66 cols
#define B_TILE  (B_ROWS * 128)           // 33792 B per split
#define B_STAGE (2 * B_TILE)             // 67584 B (hi+lo)
#define B_OFF   (2 * A_STAGE)            // B stages start after A stages
#define CONV_SMEM (2 * A_STAGE + 2 * B_STAGE + 1024)

// ======================= helpers =======================
__device__ __forceinline__ uint32_t smem_u32(const void* p) {
    uint32_t a;
    asm("{ .reg .u64 t; cvta.to.shared.u64 t, %1; cvt.u32.u64 %0, t; }" : "=r"(a) : "l"(p));
    return a;
}
__device__ __forceinline__ void ldsm_x4(uint32_t* r, uint32_t addr) {
    asm volatile("ldmatrix.sync.aligned.m8n8.x4.shared.b16 {%0,%1,%2,%3}, [%4];"
        : "=r"(r[0]), "=r"(r[1]), "=r"(r[2]), "=r"(r[3]) : "r"(addr));
}
__device__ __forceinline__ void mma16816(float* d, const uint32_t* a, const uint32_t* b) {
    asm volatile("mma.sync.aligned.m16n8k16.row.col.f32.f16.f16.f32 "
        "{%0,%1,%2,%3}, {%4,%5,%6,%7}, {%8,%9}, {%0,%1,%2,%3};"
        : "+f"(d[0]), "+f"(d[1]), "+f"(d[2]), "+f"(d[3])
        : "r"(a[0]), "r"(a[1]), "r"(a[2]), "r"(a[3]), "r"(b[0]), "r"(b[1]));
}
__device__ __forceinline__ void cp_async16(uint32_t saddr, const void* gaddr) {
    asm volatile("cp.async.cg.shared.global [%0], [%1], 16;" :: "r"(saddr), "l"(gaddr) : "memory");
}
#define CP_COMMIT() asm volatile("cp.async.commit_group;" ::: "memory")
#define CP_WAIT0()  asm volatile("cp.async.wait_group 0;" ::: "memory")

__device__ __forceinline__ float sigm(float v) { return 1.0f / (1.0f + expf(-v)); }

// ======================= device globals =======================
__device__ float g_A[3][BUFSZ];
__device__ float g_rh[NNODE][BUFSZ];
__device__ float g_z[NNODE][BUFSZ];

// fp16 hi/lo pairs are the ONLY storage for h / chsum / rh-conv-input / vis / V1
__device__ __align__(16) __half g_visT16[2][BUFSZ];
__device__ __align__(16) __half g_V116[2][BUFSZ];
__device__ __align__(16) __half g_h16[NNODE][2][BUFSZ];
__device__ __align__(16) __half g_cs16[NNODE][2][BUFSZ];
__device__ __align__(16) __half g_rh16[NNODE][2][BUFSZ];

__device__ __align__(16) __half g_wtc[6][2][9][512][512];   // [w*2+half][split][tap][o][c]
__device__ __align__(16) __half g_mtc[2][512][512];         // mconv vis half [split][o][c]

__device__ float g_lb[NNODE][CH];
__device__ float g_wsum[3][9][CH * CH];
__device__ float g_bmap[3][NNODE][9 * CH];

__device__ int g_level[NNODE];
__device__ int g_nchild[NNODE];
__device__ int g_child[NNODE][NNODE];
__device__ int g_edgeP[NNODE];
__device__ int g_edgeC[NNODE];
__device__ int g_nedge;
__device__ int g_root;

// ======================= tree prep =======================
__global__ void k_prep(const int* adj) {
    for (int n = 0; n < NNODE; ++n) g_nchild[n] = 0;
    int ne = 0;
    for (int p = 0; p < NNODE; ++p)
        for (int c = 0; c < NNODE; ++c)
            if (adj[p * NNODE + c] > 0) {
                g_child[p][g_nchild[p]++] = c;
                g_edgeP[ne] = p; g_edgeC[ne] = c; ++ne;
            }
    g_nedge = ne;
    for (int n = 0; n < NNODE; ++n) g_level[n] = 0;
    for (int it = 0; it < NNODE; ++it)
        for (int p = 0; p < NNODE; ++p)
            if (g_nchild[p] > 0) {
                int m = 0;
                for (int i = 0; i < g_nchild[p]; ++i) {
                    int lv = g_level[g_child[p][i]];
                    if (lv > m) m = lv;
                }
                g_level[p] = m + 1;
            }
    for (int c = 0; c < NNODE; ++c) {
        int cs = 0;
        for (int p = 0; p < NNODE; ++p) cs += adj[p * NNODE + c];
        if (cs == 0) { g_root = c; break; }
    }
}

// ======================= zero borders of fp16 conv-input planes =======================
__device__ __forceinline__ __half* hplane(int i) {
    if (i < 2) return g_visT16[i];
    if (i < 4) return g_V116[i - 2];
    i -= 4;
    if (i < 40) return g_h16[i >> 1][i & 1];
    i -= 40;
    if (i < 40) return g_cs16[i >> 1][i & 1];
    i -= 40;
    return g_rh16[i >> 1][i & 1];
}
__global__ void k_zero() {
    __half* p = hplane(blockIdx.y);
    int i = blockIdx.x * 256 + threadIdx.x;           // 260 border px * 512 ch
    int c = i & 511; int bi = i >> 9;
    int pp;
    if (bi < 66) pp = bi;
    else if (bi < 132) pp = 65 * PSTR + (bi - 66);
    else { int j = bi - 132; int y = 1 + (j >> 1); int x = (j & 1) * 65; pp = y * PSTR + x; }
    p[(size_t)pp * 512 + c] = __float2half(0.0f);
}

// ======================= vis NCHW -> padded NHWC fp16 hi/lo =======================
__global__ __launch_bounds__(256) void k_tvis(const float* vis) {
    __shared__ float sm[64][129];
    int y = blockIdx.x; int cc = blockIdx.y;
    for (int i = threadIdx.x; i < 64 * 128; i += 256) {
        int c = i >> 6, x = i & 63;
        sm[x][c] = vis[(size_t)(cc * 128 + c) * 4096 + y * 64 + x];
    }
    __syncthreads();
    for (int i = threadIdx.x; i < 64 * 128; i += 256) {
        int x = i >> 7, c = i & 127;
        float v = sm[x][c];
        size_t idx = (size_t)((y + 1) * PSTR + x + 1) * 512 + cc * 128 + c;
        __half hh = __float2half_rn(v);
        g_visT16[0][idx] = hh;
        g_visT16[1][idx] = __float2half_rn(v - __half2float(hh));
    }
}

// ======================= weight packing (fp16 hi/lo, [t][o][c]) =======================
__global__ void k_packtc(const float* rw, const float* uw, const float* ow, const float* mw) {
    size_t idx = (size_t)blockIdx.x * 256 + threadIdx.x;
    const size_t tot = (size_t)6 * 9 * 512 * 512;
    if (idx < tot) {
        int c = idx & 511; size_t r = idx >> 9;
        int o = r & 511; r >>= 9;
        int t = (int)(r % 9); r /= 9;
        int wh = (int)r; int w = wh >> 1, half = wh & 1;
        const float* wp = (w == 0) ? rw : (w == 1) ? uw : ow;
        float v = wp[((size_t)o * 1024 + half * 512 + c) * 9 + t];
        __half hi = __float2half_rn(v);
        float lo = v - __half2float(hi);
        g_wtc[wh][0][t][o][c] = hi;
        g_wtc[wh][1][t][o][c] = __float2half_rn(lo);
    } else if (idx < tot + (size_t)512 * 512) {
        size_t j = idx - tot; int c = (int)(j & 511); int o = (int)(j >> 9);
        float v = mw[(size_t)o * 812 + c];
        __half hi = __float2half_rn(v);
        float lo = v - __half2float(hi);
        g_mtc[0][o][c] = hi;
        g_mtc[1][o][c] = __float2half_rn(lo);
    }
}

// ======================= lb / wsum / bmap =======================
__global__ void k_lb(const float* lang, const float* mw, const float* mb) {
    int n = blockIdx.x; int c = threadIdx.x;
    float acc = mb[c];
    const float* wrow = mw + (size_t)c * 812 + 512;
    const float* lrow = lang + n * 300;
    for (int cl = 0; cl < 300; ++cl) acc += wrow[cl] * lrow[cl];
    g_lb[n][c] = acc;
}

__global__ void k_wsum(const float* rw, const float* uw, const float* ow) {
    int idx = blockIdx.x * 256 + threadIdx.x;
    int o = idx & 511; int c = (idx >> 9) & 511; int w = idx >> 18;
    const float* wp = (w == 0) ? rw : (w == 1) ? uw : ow;
    float t[9];
    const float* base = wp + ((size_t)o * 1024 + c) * 9;
#pragma unroll
    for (int k = 0; k < 9; ++k) t[k] = base[k];
#pragma unroll
    for (int cls = 0; cls < 9; ++cls) {
        int yt = cls / 3, xt = cls % 3;
        int kh0 = (yt == 0) ? 1 : 0, kh1 = (yt == 2) ? 1 : 2;
        int kw0 = (xt == 0) ? 1 : 0, kw1 = (xt == 2) ? 1 : 2;
        float s = 0.0f;
        for (int kh = kh0; kh <= kh1; ++kh)
            for (int kw = kw0; kw <= kw1; ++kw) s += t[kh * 3 + kw];
        g_wsum[w][cls][(size_t)c * CH + o] = s;
    }
}

__global__ __launch_bounds__(256) void k_bmap(const float* rb, const float* ub, const float* ob) {
    __shared__ float lb_s[NNODE * CH];
    int tid = threadIdx.x;
    int o = blockIdx.x * 256 + tid;
    int w = blockIdx.y / 9;
    int cls = blockIdx.y % 9;
    const float* lbf = &g_lb[0][0];
    for (int j = tid; j < NNODE * CH; j += 256) lb_s[j] = lbf[j];
    __syncthreads();
    const float* bptr = (w == 0) ? rb : (w == 1) ? ub : ob;
    float acc[NNODE];
    float bv = bptr[o];
#pragma unroll
    for (int n = 0; n < NNODE; ++n) acc[n] = bv;
    const float* ws = g_wsum[w][cls];
    for (int c = 0; c < CH; ++c) {
        float wv = ws[(size_t)c * CH + o];
#pragma unroll
        for (int n = 0; n < NNODE; ++n) acc[n] += lb_s[n * CH + c] * wv;
    }
#pragma unroll
    for (int n = 0; n < NNODE; ++n) g_bmap[w][n][cls * CH + o] = acc[n];
}

// ======================= A loader: one (weight-tap, c-chunk) weight tile =======================
// wt is the WEIGHT plane index (0 for mode 4 / mconv; tap index otherwise)
// both=0: load only the hi plane
__device__ __forceinline__ void load_A(
    int tid, uint32_t abase,
    const __half* wA0, const __half* wA1,
    int wt, int c0, int coBase, int both)
{
#pragma unroll
    for (int p = 0; p < 4; ++p) {
        int idx = tid * 4 + p;                 // 0..1023
        int o = idx >> 3; int kc = idx & 7;
        size_t goff = (size_t)wt * 262144 + (size_t)(coBase + o) * 512 + c0 + kc * 8;
        uint32_t so = (uint32_t)o * 128 + ((kc ^ (o & 7)) << 4);
        cp_async16(abase + so, wA0 + goff);
        if (both) cp_async16(abase + A_TILE + so, wA1 + goff);
    }
}

// ======================= B halo loader: quarter of a c-chunk halo =======================
// halo = padded rows [y0, y0+4) x cols [0, 66) for channels [c0, c0+64)
// lo=0: skip the lo plane (1-product recurrence mode)
__device__ __forceinline__ void load_Bq(
    int tid, uint32_t bbase,
    const __half* inH, const __half* inL,
    int c0, int y0, int part, int lo)
{
#pragma unroll
    for (int it = 0; it < 3; ++it) {
        int idx0 = it * 256 + tid;
        if (idx0 < 528) {
            int idx = part * 528 + idx0;       // 0..2111
            int p = idx >> 3; int kc = idx & 7;
            int pr = p / 66, pc = p % 66;
            size_t goff = (size_t)((y0 + pr) * PSTR + pc) * 512 + c0 + kc * 8;
            uint32_t so = (uint32_t)p * 128 + ((kc ^ (p & 7)) << 4);
            cp_async16(bbase + so, inH + goff);
            if (lo) cp_async16(bbase + B_TILE + so, inL + goff);
        }
    }
}

// ======================= tensor-core conv (tap-reuse B halo in smem) =======================
// mode 4: V1 = mconv_vis(visT16) -> V116              (3-product, weight plane 0)
// mode 0: g_A[bz] = conv3(V116, w[bz] first half)     (3-product)
// mode 12: bz<20: reset per edge -> atomic rh ; bz>=20: update -> z   (1-product)
// mode 3: output conv (B=rh16) -> h16                                  (1-product)
__global__ __launch_bounds__(256) void k_conv(int mode, int round) {
    int bz = blockIdx.z;
    const __half* inH; const __half* inL;
    const __half* wA0; const __half* wA1;
    int emode, node = -1, outsel = 0;

    if (mode == 4) {
        inH = g_visT16[0]; inL = g_visT16[1];
        wA0 = &g_mtc[0][0][0]; wA1 = &g_mtc[1][0][0]; emode = 4;
    } else if (mode == 0) {
        inH = g_V116[0]; inL = g_V116[1];
        int wh = bz * 2;
        wA0 = &g_wtc[wh][0][0][0][0]; wA1 = &g_wtc[wh][1][0][0][0];
        emode = 0; outsel = bz;
    } else if (mode == 12) {
        if (bz < NNODE) {
            if (bz >= g_nedge) return;
            node = g_edgeP[bz];
            if (g_level[node] != round) return;
            int child = g_edgeC[bz];
            inH = g_h16[child][0]; inL = g_h16[child][1];
            wA0 = &g_wtc[1][0][0][0][0]; wA1 = &g_wtc[1][1][0][0][0];
            emode = 1;
        } else {
            node = bz - NNODE;
            if (g_level[node] != round || g_nchild[node] == 0) return;
            inH = g_cs16[node][0]; inL = g_cs16[node][1];
            wA0 = &g_wtc[3][0][0][0][0]; wA1 = &g_wtc[3][1][0][0][0];
            emode = 2;
        }
    } else {
        node = bz;
        if (g_level[node] != round || g_nchild[node] == 0) return;
        inH = g_rh16[node][0]; inL = g_rh16[node][1];
        wA0 = &g_wtc[5][0][0][0][0]; wA1 = &g_wtc[5][1][0][0][0];
        emode = 3;
    }

    // precompute fields use 3 products; recurrence convs use 1 (Ah*Bh only)
    const int nprod = (emode == 0 || emode == 4) ? 3 : 1;
    const int blo = (nprod >= 2) ? 1 : 0;

    extern __shared__ char dsm[];
    uint32_t sraw = smem_u32(dsm);
    uint32_t sbase = (sraw + 1023u) & ~1023u;

    int tid = threadIdx.x;
    int lane = tid & 31, wid = tid >> 5;
    int wm = wid >> 2, wn = wid & 3;        // warp tile: M64 x N32
    int lr = lane & 7, lg = lane >> 3;

    int y0 = blockIdx.x * 2;
    int coBase = blockIdx.y * 128;
    int tap_lo = (mode == 4) ? 4 : 0;
    int tap_hi = (mode == 4) ? 4 : 8;

    // B-fragment pixel geometry (independent of tap)
    int nrow0 = wn * 32 + 0 * 16 + lr + ((lg >> 1) << 3);
    int nrow1 = wn * 32 + 1 * 16 + lr + ((lg >> 1) << 3);
    int ry0_ = nrow0 >> 6, xx0_ = nrow0 & 63;
    int ry1_ = nrow1 >> 6, xx1_ = nrow1 & 63;

    float acc[4][4][4];
#pragma unroll
    for (int a = 0; a < 4; ++a)
#pragma unroll
        for (int b = 0; b < 4; ++b)
#pragma unroll
            for (int c = 0; c < 4; ++c) acc[a][b][c] = 0.0f;

    // ---------- prologue ----------
    {
        uint32_t b0 = sbase + B_OFF;
#pragma unroll
        for (int part = 0; part < 4; ++part)
            load_Bq(tid, b0, inH, inL, 0, y0, part, blo);
        load_A(tid, sbase, wA0, wA1, (mode == 4) ? 0 : tap_lo, 0, coBase, nprod == 3);
        CP_COMMIT();
        CP_WAIT0();
        __syncthreads();
    }

    int as = 0, bs = 0;
    for (int q = 0; q < 8; ++q) {
        int c0next = (q + 1) << 6;
        for (int tp = tap_lo; tp <= tap_hi; ++tp) {
            bool last = (q == 7) && (tp == tap_hi);
            if (!last) {
                int nq = q, nt = tp + 1;
                if (nt > tap_hi) { nq = q + 1; nt = tap_lo; }
                int wt = (mode == 4) ? 0 : nt;       // weight plane index
                load_A(tid, sbase + (as ^ 1) * A_STAGE, wA0, wA1, wt, nq << 6, coBase, nprod == 3);
                if (q < 7) {
                    int part = tp - tap_lo;
                    uint32_t bn = sbase + B_OFF + (bs ^ 1) * B_STAGE;
                    if (mode == 4) {
#pragma unroll
                        for (int pp = 0; pp < 4; ++pp)
                            load_Bq(tid, bn, inH, inL, c0next, y0, pp, blo);
                    } else if (part < 4) {
                        load_Bq(tid, bn, inH, inL, c0next, y0, part, blo);
                    }
                }
                CP_COMMIT();
            }

            // ---- mma on A[as], B window of stage bs at tap tp ----
            {
                int dy = tp / 3, dx = tp % 3;
                int p0 = (ry0_ + dy) * 66 + xx0_ + dx;
                int p1 = (ry1_ + dy) * 66 + xx1_ + dx;
                uint32_t stA = sbase + as * A_STAGE;
                uint32_t stAl = stA + A_TILE;
                uint32_t stB = sbase + B_OFF + bs * B_STAGE;
                uint32_t stBl = stB + B_TILE;
                uint32_t rowoff0 = (uint32_t)p0 * 128;
                uint32_t rowoff1 = (uint32_t)p1 * 128;
                int sw0 = p0 & 7, sw1 = p1 & 7;

#pragma unroll
                for (int ks = 0; ks < 4; ++ks) {
                    int kc0 = ks * 2;
                    uint32_t af[4][4], bhf[2][4], blf[2][4];
#pragma unroll
                    for (int tm = 0; tm < 4; ++tm) {
                        int row = wm * 64 + tm * 16 + lr + ((lg & 1) << 3);
                        int ch = kc0 + (lg >> 1);
                        ldsm_x4(af[tm], stA + row * 128 + ((ch ^ (row & 7)) << 4));
                    }
                    {
                        int ch = kc0 + (lg & 1);
                        uint32_t o0 = rowoff0 + (uint32_t)((ch ^ sw0) << 4);
                        uint32_t o1 = rowoff1 + (uint32_t)((ch ^ sw1) << 4);
                        ldsm_x4(bhf[0], stB + o0);
                        ldsm_x4(bhf[1], stB + o1);
                        if (blo) {
                            ldsm_x4(blf[0], stBl + o0);
                            ldsm_x4(blf[1], stBl + o1);
                        }
                    }
#pragma unroll
                    for (int tm = 0; tm < 4; ++tm)
#pragma unroll
                        for (int tn = 0; tn < 4; ++tn)
                            mma16816(acc[tm][tn], af[tm], &bhf[tn >> 1][(tn & 1) * 2]);
                    if (blo) {
#pragma unroll
                        for (int tm = 0; tm < 4; ++tm)
#pragma unroll
                            for (int tn = 0; tn < 4; ++tn)
                                mma16816(acc[tm][tn], af[tm], &blf[tn >> 1][(tn & 1) * 2]);
                    }
                    if (nprod == 3) {
#pragma unroll
                        for (int tm = 0; tm < 4; ++tm) {
                            int row = wm * 64 + tm * 16 + lr + ((lg & 1) << 3);
                            int ch = kc0 + (lg >> 1);
                            ldsm_x4(af[tm], stAl + row * 128 + ((ch ^ (row & 7)) << 4));
                        }
#pragma unroll
                        for (int tm = 0; tm < 4; ++tm)
#pragma unroll
                            for (int tn = 0; tn < 4; ++tn)
                                mma16816(acc[tm][tn], af[tm], &bhf[tn >> 1][(tn & 1) * 2]);
                    }
                }
            }

            if (!last) CP_WAIT0();
            __syncthreads();
            as ^= 1;
        }
        bs ^= 1;
    }

    // ---------- epilogue ----------
#pragma unroll
    for (int tm = 0; tm < 4; ++tm) {
#pragma unroll
        for (int tn = 0; tn < 4; ++tn) {
#pragma unroll
            for (int j = 0; j < 4; ++j) {
                int m = wm * 64 + tm * 16 + (lane >> 2) + ((j >> 1) << 3);
                int n = wn * 32 + tn * 8 + ((lane & 3) << 1) + (j & 1);
                int o = coBase + m;
                int ry = n >> 6, x = n & 63;
                int y = y0 + ry;
                size_t pidx = (size_t)((y + 1) * PSTR + x + 1) * 512 + o;
                float v = acc[tm][tn][j];
                if (emode == 4) {
                    __half hh = __float2half_rn(v);
                    g_V116[0][pidx] = hh;
                    g_V116[1][pidx] = __float2half_rn(v - __half2float(hh));
                } else if (emode == 0) {
                    g_A[outsel][pidx] = v;
                } else {
                    int yt = (y == 0) ? 0 : ((y == 63) ? 2 : 1);
                    int xt = (x == 0) ? 0 : ((x == 63) ? 2 : 1);
                    int cls = yt * 3 + xt;
                    if (emode == 1) {
                        float r = sigm(v + g_A[0][pidx] + g_bmap[0][node][cls * CH + o]);
                        float hval = __half2float(inH[pidx]) + __half2float(inL[pidx]);
                        atomicAdd(&g_rh[node][pidx], r * hval);
                    } else if (emode == 2) {
                        g_z[node][pidx] = sigm(v + g_A[1][pidx] + g_bmap[1][node][cls * CH + o]);
                    } else {
                        float ri = tanhf(v + g_A[2][pidx] + g_bmap[2][node][cls * CH + o]);
                        float zz = g_z[node][pidx];
                        float cs = __half2float(g_cs16[node][0][pidx]) +
                                   __half2float(g_cs16[node][1][pidx]);
                        float hv = (1.0f - zz) * ri + zz * cs;
                        __half hh = __float2half_rn(hv);
                        g_h16[node][0][pidx] = hh;
                        g_h16[node][1][pidx] = __float2half_rn(hv - __half2float(hh));
                    }
                }
            }
        }
    }
}

// ======================= ch_sum (fp16 hi/lo) + zero rh =======================
__global__ void k_chsum(int round) {
    int n = blockIdx.y;
    if (g_level[n] != round || g_nchild[n] == 0) return;
    int nc = g_nchild[n];
    size_t base = (size_t)blockIdx.x * 2048 + threadIdx.x;
#pragma unroll
    for (int e = 0; e < 8; ++e) {
        size_t i = base + (size_t)e * 256;
        float s = 0.0f;
        for (int ci = 0; ci < nc; ++ci) {
            int c = g_child[n][ci];
            s += __half2float(g_h16[c][0][i]) + __half2float(g_h16[c][1][i]);
        }
        __half hh = __float2half_rn(s);
        g_cs16[n][0][i] = hh;
        g_cs16[n][1][i] = __float2half_rn(s - __half2float(hh));
        g_rh[n][i] = 0.0f;
    }
}

// ======================= rh -> fp16 hi (per round, active nodes; lo unused) =======================
__global__ void k_cvtrh(int round) {
    int n = blockIdx.y;
    if (g_level[n] != round || g_nchild[n] == 0) return;
    size_t base = (size_t)blockIdx.x * 2048 + threadIdx.x;
#pragma unroll
    for (int e = 0; e < 8; ++e) {
        size_t i = base + (size_t)e * 256;
        g_rh16[n][0][i] = __float2half_rn(g_rh[n][i]);
    }
}

// ======================= leaves =======================
__global__ void k_leaf() {
    int n = blockIdx.y;
    if (g_nchild[n] != 0) return;
    size_t base = (size_t)blockIdx.x * 2048 + threadIdx.x;
#pragma unroll
    for (int e = 0; e < 8; ++e) {
        size_t i = base + (size_t)e * 256;
        int c = (int)(i & 511);
        int pp = (int)(i >> 9);
        int y = pp / PSTR - 1, x = pp % PSTR - 1;
        float hv = 0.0f;
        if ((unsigned)y < 64u && (unsigned)x < 64u) {
            int yt = (y == 0) ? 0 : ((y == 63) ? 2 : 1);
            int xt = (x == 0) ? 0 : ((x == 63) ? 2 : 1);
            int cls = yt * 3 + xt;
            float zu = sigm(g_A[1][i] + g_bmap[1][n][cls * CH + c]);
            float ro = tanhf(g_A[2][i] + g_bmap[2][n][cls * CH + c]);
            hv = (1.0f - zu) * ro;
        }
        __half hh = __float2half_rn(hv);
        g_h16[n][0][i] = hh;
        g_h16[n][1][i] = __float2half_rn(hv - __half2float(hh));
    }
}

// ======================= output: padded NHWC fp16 hi/lo -> NCHW fp32 =======================
__global__ __launch_bounds__(256) void k_copyout(float* out) {
    __shared__ float sm[64][129];
    int root = g_root;
    int y = blockIdx.x; int oc = blockIdx.y;
    const __half* srcH = g_h16[root][0] + (size_t)((y + 1) * PSTR + 1) * 512 + oc * 128;
    const __half* srcL = g_h16[root][1] + (size_t)((y + 1) * PSTR + 1) * 512 + oc * 128;
    for (int i = threadIdx.x; i < 64 * 128; i += 256) {
        int x = i >> 7, o = i & 127;
        sm[x][o] = __half2float(srcH[(size_t)x * 512 + o]) +
                   __half2float(srcL[(size_t)x * 512 + o]);
    }
    __syncthreads();
    for (int i = threadIdx.x; i < 64 * 128; i += 256) {
        int o = i >> 6, x = i & 63;
        out[(size_t)(oc * 128 + o) * 4096 + y * 64 + x] = sm[x][o];
    }
}

// ======================= launch =======================
extern "C" void kernel_launch(void* const* d_in, const int* in_sizes, int n_in,
                              void* d_out, int out_size) {
    const float* vis  = (const float*)d_in[0];
    const float* lang = (const float*)d_in[1];
    const int*   adj  = (const int*)d_in[2];
    const float* mw   = (const float*)d_in[3];
    const float* mb   = (const float*)d_in[4];
    const float* rw   = (const float*)d_in[5];
    const float* rb   = (const float*)d_in[6];
    const float* uw   = (const float*)d_in[7];
    const float* ub   = (const float*)d_in[8];
    const float* ow   = (const float*)d_in[9];
    const float* ob   = (const float*)d_in[10];
    float* out = (float*)d_out;

    cudaFuncSetAttribute(k_conv, cudaFuncAttributeMaxDynamicSharedMemorySize, CONV_SMEM);

    k_prep<<<1, 1>>>(adj);
    k_zero<<<dim3(520, 124), 256>>>();
    k_tvis<<<dim3(64, 4), 256>>>(vis);
    {
        size_t tot = (size_t)6 * 9 * 512 * 512 + (size_t)512 * 512;
        k_packtc<<<(unsigned)((tot + 255) / 256), 256>>>(rw, uw, ow, mw);
    }
    k_wsum<<<(3 * CH * CH) / 256, 256>>>(rw, uw, ow);
    k_lb<<<NNODE, CH>>>(lang, mw, mb);
    k_bmap<<<dim3(2, 27), 256>>>(rb, ub, ob);

    k_conv<<<dim3(32, 4, 1), 256, CONV_SMEM>>>(4, 0);   // V1 -> V116 (3-product)
    k_conv<<<dim3(32, 4, 3), 256, CONV_SMEM>>>(0, 0);   // A_r, A_u, A_o (3-product)
    k_leaf<<<dim3(1089, NNODE), 256>>>();

    for (int t = 1; t <= MAXROUND; ++t) {
        k_chsum<<<dim3(1089, NNODE), 256>>>(t);
        k_conv<<<dim3(32, 4, 2 * NNODE), 256, CONV_SMEM>>>(12, t);  // reset + update (1-product)
        k_cvtrh<<<dim3(1089, NNODE), 256>>>(t);
        k_conv<<<dim3(32, 4, NNODE), 256, CONV_SMEM>>>(3, t);       // output (1-product)
    }
    k_copyout<<<dim3(64, 4), 256>>>(out);
}

// round 12
// speedup vs baseline: 3.1901x; 1.3773x over previous
#include <cuda_runtime.h>
#include <cuda_fp16.h>
#include <cstdint>

#define CH    512
#define NNODE 20
#define PSTR  66
#define BUFSZ (PSTR * PSTR * CH)
#define MAXROUND 19

#define A_TILE  16384                    // per split: 128 rows x 128B
#define B_TILE  33792                    // 264 rows x 128B per split
// PRE layout: A stages 32KB (hi+lo), B stages 67.6KB (hi+lo)
#define CONV_SMEM_PRE (2 * 32768 + 2 * 67584 + 1024)
// REC layout: A stages 16KB (hi), B stages 33.8KB (hi) -> 2 CTAs/SM
#define CONV_SMEM_REC (2 * 16384 + 2 * 33792 + 1024)

// ======================= helpers =======================
__device__ __forceinline__ uint32_t smem_u32(const void* p) {
    uint32_t a;
    asm("{ .reg .u64 t; cvta.to.shared.u64 t, %1; cvt.u32.u64 %0, t; }" : "=r"(a) : "l"(p));
    return a;
}
__device__ __forceinline__ void ldsm_x4(uint32_t* r, uint32_t addr) {
    asm volatile("ldmatrix.sync.aligned.m8n8.x4.shared.b16 {%0,%1,%2,%3}, [%4];"
        : "=r"(r[0]), "=r"(r[1]), "=r"(r[2]), "=r"(r[3]) : "r"(addr));
}
__device__ __forceinline__ void mma16816(float* d, const uint32_t* a, const uint32_t* b) {
    asm volatile("mma.sync.aligned.m16n8k16.row.col.f32.f16.f16.f32 "
        "{%0,%1,%2,%3}, {%4,%5,%6,%7}, {%8,%9}, {%0,%1,%2,%3};"
        : "+f"(d[0]), "+f"(d[1]), "+f"(d[2]), "+f"(d[3])
        : "r"(a[0]), "r"(a[1]), "r"(a[2]), "r"(a[3]), "r"(b[0]), "r"(b[1]));
}
__device__ __forceinline__ void cp_async16(uint32_t saddr, const void* gaddr) {
    asm volatile("cp.async.cg.shared.global [%0], [%1], 16;" :: "r"(saddr), "l"(gaddr) : "memory");
}
#define CP_COMMIT() asm volatile("cp.async.commit_group;" ::: "memory")
#define CP_WAIT0()  asm volatile("cp.async.wait_group 0;" ::: "memory")

__device__ __forceinline__ float sigm(float v) { return 1.0f / (1.0f + expf(-v)); }

// ======================= device globals =======================
__device__ float g_A[3][BUFSZ];
__device__ float g_rh[NNODE][BUFSZ];
__device__ float g_z[NNODE][BUFSZ];

__device__ __align__(16) __half g_visT16[2][BUFSZ];
__device__ __align__(16) __half g_V116[2][BUFSZ];
__device__ __align__(16) __half g_h16[NNODE][2][BUFSZ];
__device__ __align__(16) __half g_cs16[NNODE][2][BUFSZ];
__device__ __align__(16) __half g_rh16[NNODE][2][BUFSZ];

__device__ __align__(16) __half g_wtc[6][2][9][512][512];   // [w*2+half][split][tap][o][c]
__device__ __align__(16) __half g_mtc[2][512][512];         // mconv vis half [split][o][c]

__device__ float g_lb[NNODE][CH];
__device__ float g_wsum[3][9][CH * CH];
__device__ float g_bmap[3][NNODE][9 * CH];

__device__ int g_level[NNODE];
__device__ int g_nchild[NNODE];
__device__ int g_child[NNODE][NNODE];
__device__ int g_edgeP[NNODE];
__device__ int g_edgeC[NNODE];
__device__ int g_nedge;
__device__ int g_root;

// ======================= tree prep =======================
__global__ void k_prep(const int* adj) {
    for (int n = 0; n < NNODE; ++n) g_nchild[n] = 0;
    int ne = 0;
    for (int p = 0; p < NNODE; ++p)
        for (int c = 0; c < NNODE; ++c)
            if (adj[p * NNODE + c] > 0) {
                g_child[p][g_nchild[p]++] = c;
                g_edgeP[ne] = p; g_edgeC[ne] = c; ++ne;
            }
    g_nedge = ne;
    for (int n = 0; n < NNODE; ++n) g_level[n] = 0;
    for (int it = 0; it < NNODE; ++it)
        for (int p = 0; p < NNODE; ++p)
            if (g_nchild[p] > 0) {
                int m = 0;
                for (int i = 0; i < g_nchild[p]; ++i) {
                    int lv = g_level[g_child[p][i]];
                    if (lv > m) m = lv;
                }
                g_level[p] = m + 1;
            }
    for (int c = 0; c < NNODE; ++c) {
        int cs = 0;
        for (int p = 0; p < NNODE; ++p) cs += adj[p * NNODE + c];
        if (cs == 0) { g_root = c; break; }
    }
}

// ======================= zero borders of fp16 conv-input planes =======================
__device__ __forceinline__ __half* hplane(int i) {
    if (i < 2) return g_visT16[i];
    if (i < 4) return g_V116[i - 2];
    i -= 4;
    if (i < 40) return g_h16[i >> 1][i & 1];
    i -= 40;
    if (i < 40) return g_cs16[i >> 1][i & 1];
    i -= 40;
    return g_rh16[i >> 1][i & 1];
}
__global__ void k_zero() {
    __half* p = hplane(blockIdx.y);
    int i = blockIdx.x * 256 + threadIdx.x;           // 260 border px * 512 ch
    int c = i & 511; int bi = i >> 9;
    int pp;
    if (bi < 66) pp = bi;
    else if (bi < 132) pp = 65 * PSTR + (bi - 66);
    else { int j = bi - 132; int y = 1 + (j >> 1); int x = (j & 1) * 65; pp = y * PSTR + x; }
    p[(size_t)pp * 512 + c] = __float2half(0.0f);
}

// ======================= vis NCHW -> padded NHWC fp16 hi/lo =======================
__global__ __launch_bounds__(256) void k_tvis(const float* vis) {
    __shared__ float sm[64][129];
    int y = blockIdx.x; int cc = blockIdx.y;
    for (int i = threadIdx.x; i < 64 * 128; i += 256) {
        int c = i >> 6, x = i & 63;
        sm[x][c] = vis[(size_t)(cc * 128 + c) * 4096 + y * 64 + x];
    }
    __syncthreads();
    for (int i = threadIdx.x; i < 64 * 128; i += 256) {
        int x = i >> 7, c = i & 127;
        float v = sm[x][c];
        size_t idx = (size_t)((y + 1) * PSTR + x + 1) * 512 + cc * 128 + c;
        __half hh = __float2half_rn(v);
        g_visT16[0][idx] = hh;
        g_visT16[1][idx] = __float2half_rn(v - __half2float(hh));
    }
}

// ======================= weight packing (fp16 hi/lo, [t][o][c]) =======================
__global__ void k_packtc(const float* rw, const float* uw, const float* ow, const float* mw) {
    size_t idx = (size_t)blockIdx.x * 256 + threadIdx.x;
    const size_t tot = (size_t)6 * 9 * 512 * 512;
    if (idx < tot) {
        int c = idx & 511; size_t r = idx >> 9;
        int o = r & 511; r >>= 9;
        int t = (int)(r % 9); r /= 9;
        int wh = (int)r; int w = wh >> 1, half = wh & 1;
        const float* wp = (w == 0) ? rw : (w == 1) ? uw : ow;
        float v = wp[((size_t)o * 1024 + half * 512 + c) * 9 + t];
        __half hi = __float2half_rn(v);
        float lo = v - __half2float(hi);
        g_wtc[wh][0][t][o][c] = hi;
        g_wtc[wh][1][t][o][c] = __float2half_rn(lo);
    } else if (idx < tot + (size_t)512 * 512) {
        size_t j = idx - tot; int c = (int)(j & 511); int o = (int)(j >> 9);
        float v = mw[(size_t)o * 812 + c];
        __half hi = __float2half_rn(v);
        float lo = v - __half2float(hi);
        g_mtc[0][o][c] = hi;
        g_mtc[1][o][c] = __float2half_rn(lo);
    }
}

// ======================= lb / wsum / bmap =======================
__global__ void k_lb(const float* lang, const float* mw, const float* mb) {
    int n = blockIdx.x; int c = threadIdx.x;
    float acc = mb[c];
    const float* wrow = mw + (size_t)c * 812 + 512;
    const float* lrow = lang + n * 300;
    for (int cl = 0; cl < 300; ++cl) acc += wrow[cl] * lrow[cl];
    g_lb[n][c] = acc;
}

__global__ void k_wsum(const float* rw, const float* uw, const float* ow) {
    int idx = blockIdx.x * 256 + threadIdx.x;
    int o = idx & 511; int c = (idx >> 9) & 511; int w = idx >> 18;
    const float* wp = (w == 0) ? rw : (w == 1) ? uw : ow;
    float t[9];
    const float* base = wp + ((size_t)o * 1024 + c) * 9;
#pragma unroll
    for (int k = 0; k < 9; ++k) t[k] = base[k];
#pragma unroll
    for (int cls = 0; cls < 9; ++cls) {
        int yt = cls / 3, xt = cls % 3;
        int kh0 = (yt == 0) ? 1 : 0, kh1 = (yt == 2) ? 1 : 2;
        int kw0 = (xt == 0) ? 1 : 0, kw1 = (xt == 2) ? 1 : 2;
        float s = 0.0f;
        for (int kh = kh0; kh <= kh1; ++kh)
            for (int kw = kw0; kw <= kw1; ++kw) s += t[kh * 3 + kw];
        g_wsum[w][cls][(size_t)c * CH + o] = s;
    }
}

__global__ __launch_bounds__(256) void k_bmap(const float* rb, const float* ub, const float* ob) {
    __shared__ float lb_s[NNODE * CH];
    int tid = threadIdx.x;
    int o = blockIdx.x * 256 + tid;
    int w = blockIdx.y / 9;
    int cls = blockIdx.y % 9;
    const float* lbf = &g_lb[0][0];
    for (int j = tid; j < NNODE * CH; j += 256) lb_s[j] = lbf[j];
    __syncthreads();
    const float* bptr = (w == 0) ? rb : (w == 1) ? ub : ob;
    float acc[NNODE];
    float bv = bptr[o];
#pragma unroll
    for (int n = 0; n < NNODE; ++n) acc[n] = bv;
    const float* ws = g_wsum[w][cls];
    for (int c = 0; c < CH; ++c) {
        float wv = ws[(size_t)c * CH + o];
#pragma unroll
        for (int n = 0; n < NNODE; ++n) acc[n] += lb_s[n * CH + c] * wv;
    }
#pragma unroll
    for (int n = 0; n < NNODE; ++n) g_bmap[w][n][cls * CH + o] = acc[n];
}

// ======================= A loader =======================
__device__ __forceinline__ void load_A(
    int tid, uint32_t abase,
    const __half* wA0, const __half* wA1,
    int wt, int c0, int coBase, int both)
{
#pragma unroll
    for (int p = 0; p < 4; ++p) {
        int idx = tid * 4 + p;                 // 0..1023
        int o = idx >> 3; int kc = idx & 7;
        size_t goff = (size_t)wt * 262144 + (size_t)(coBase + o) * 512 + c0 + kc * 8;
        uint32_t so = (uint32_t)o * 128 + ((kc ^ (o & 7)) << 4);
        cp_async16(abase + so, wA0 + goff);
        if (both) cp_async16(abase + A_TILE + so, wA1 + goff);
    }
}

// ======================= B halo loader: quarter of a c-chunk halo =======================
__device__ __forceinline__ void load_Bq(
    int tid, uint32_t bbase,
    const __half* inH, const __half* inL,
    int c0, int y0, int part, int lo)
{
#pragma unroll
    for (int it = 0; it < 3; ++it) {
        int idx0 = it * 256 + tid;
        if (idx0 < 528) {
            int idx = part * 528 + idx0;       // 0..2111
            int p = idx >> 3; int kc = idx & 7;
            int pr = p / 66, pc = p % 66;
            size_t goff = (size_t)((y0 + pr) * PSTR + pc) * 512 + c0 + kc * 8;
            uint32_t so = (uint32_t)p * 128 + ((kc ^ (p & 7)) << 4);
            cp_async16(bbase + so, inH + goff);
            if (lo) cp_async16(bbase + B_TILE + so, inL + goff);
        }
    }
}

// ======================= tensor-core conv (tap-reuse B halo in smem) =======================
// PRE=1: mode 4 (V1, 3-product) / mode 0 (A fields, 2-product), full layout, 1 CTA/SM
// PRE=0: mode 12 (reset+update) / mode 3 (output), 1-product compact layout, 2 CTAs/SM
template<int PRE>
__global__ __launch_bounds__(256, PRE ? 1 : 2) void k_conv(int mode, int round) {
    int bz = blockIdx.z;
    const __half* inH; const __half* inL;
    const __half* wA0; const __half* wA1;
    int emode, node = -1, outsel = 0;

    if (PRE) {
        if (mode == 4) {
            inH = g_visT16[0]; inL = g_visT16[1];
            wA0 = &g_mtc[0][0][0]; wA1 = &g_mtc[1][0][0]; emode = 4;
        } else {
            inH = g_V116[0]; inL = g_V116[1];
            int wh = bz * 2;
            wA0 = &g_wtc[wh][0][0][0][0]; wA1 = &g_wtc[wh][1][0][0][0];
            emode = 0; outsel = bz;
        }
    } else {
        if (mode == 12) {
            if (bz < NNODE) {
                if (bz >= g_nedge) return;
                node = g_edgeP[bz];
                if (g_level[node] != round) return;
                int child = g_edgeC[bz];
                inH = g_h16[child][0]; inL = g_h16[child][1];
                wA0 = &g_wtc[1][0][0][0][0]; wA1 = &g_wtc[1][1][0][0][0];
                emode = 1;
            } else {
                node = bz - NNODE;
                if (g_level[node] != round || g_nchild[node] == 0) return;
                inH = g_cs16[node][0]; inL = g_cs16[node][1];
                wA0 = &g_wtc[3][0][0][0][0]; wA1 = &g_wtc[3][1][0][0][0];
                emode = 2;
            }
        } else {
            node = bz;
            if (g_level[node] != round || g_nchild[node] == 0) return;
            inH = g_rh16[node][0]; inL = g_rh16[node][1];
            wA0 = &g_wtc[5][0][0][0][0]; wA1 = &g_wtc[5][1][0][0][0];
            emode = 3;
        }
    }

    // products: mode4 -> 3 (Ah*Bh + Ah*Bl + Al*Bh); mode0 -> 2 (Ah*Bh + Ah*Bl); rec -> 1
    const int nprod = PRE ? ((mode == 4) ? 3 : 2) : 1;
    const int blo = PRE ? 1 : 0;

    // stage strides depend on layout
    const uint32_t ASTG = PRE ? 32768u : 16384u;
    const uint32_t BOFFS = 2u * ASTG;
    const uint32_t BSTG = PRE ? 67584u : 33792u;

    extern __shared__ char dsm[];
    uint32_t sraw = smem_u32(dsm);
    uint32_t sbase = (sraw + 1023u) & ~1023u;

    int tid = threadIdx.x;
    int lane = tid & 31, wid = tid >> 5;
    int wm = wid >> 2, wn = wid & 3;        // warp tile: M64 x N32
    int lr = lane & 7, lg = lane >> 3;

    int y0 = blockIdx.x * 2;
    int coBase = blockIdx.y * 128;
    int tap_lo = (mode == 4) ? 4 : 0;
    int tap_hi = (mode == 4) ? 4 : 8;

    // B-fragment pixel geometry (independent of tap)
    int nrow0 = wn * 32 + 0 * 16 + lr + ((lg >> 1) << 3);
    int nrow1 = wn * 32 + 1 * 16 + lr + ((lg >> 1) << 3);
    int ry0_ = nrow0 >> 6, xx0_ = nrow0 & 63;
    int ry1_ = nrow1 >> 6, xx1_ = nrow1 & 63;

    float acc[4][4][4];
#pragma unroll
    for (int a = 0; a < 4; ++a)
#pragma unroll
        for (int b = 0; b < 4; ++b)
#pragma unroll
            for (int c = 0; c < 4; ++c) acc[a][b][c] = 0.0f;

    // ---------- prologue ----------
    {
        uint32_t b0 = sbase + BOFFS;
#pragma unroll
        for (int part = 0; part < 4; ++part)
            load_Bq(tid, b0, inH, inL, 0, y0, part, blo);
        load_A(tid, sbase, wA0, wA1, (mode == 4) ? 0 : tap_lo, 0, coBase, nprod == 3);
        CP_COMMIT();
        CP_WAIT0();
        __syncthreads();
    }

    int as = 0, bs = 0;
    for (int q = 0; q < 8; ++q) {
        int c0next = (q + 1) << 6;
        for (int tp = tap_lo; tp <= tap_hi; ++tp) {
            bool last = (q == 7) && (tp == tap_hi);
            if (!last) {
                int nq = q, nt = tp + 1;
                if (nt > tap_hi) { nq = q + 1; nt = tap_lo; }
                int wt = (mode == 4) ? 0 : nt;       // weight plane index
                load_A(tid, sbase + (as ^ 1) * ASTG, wA0, wA1, wt, nq << 6, coBase, nprod == 3);
                if (q < 7) {
                    int part = tp - tap_lo;
                    uint32_t bn = sbase + BOFFS + (bs ^ 1) * BSTG;
                    if (mode == 4) {
#pragma unroll
                        for (int pp = 0; pp < 4; ++pp)
                            load_Bq(tid, bn, inH, inL, c0next, y0, pp, blo);
                    } else if (part < 4) {
                        load_Bq(tid, bn, inH, inL, c0next, y0, part, blo);
                    }
                }
                CP_COMMIT();
            }

            // ---- mma on A[as], B window of stage bs at tap tp ----
            {
                int dy = tp / 3, dx = tp % 3;
                int p0 = (ry0_ + dy) * 66 + xx0_ + dx;
                int p1 = (ry1_ + dy) * 66 + xx1_ + dx;
                uint32_t stA = sbase + as * ASTG;
                uint32_t stAl = stA + A_TILE;
                uint32_t stB = sbase + BOFFS + bs * BSTG;
                uint32_t stBl = stB + B_TILE;
                uint32_t rowoff0 = (uint32_t)p0 * 128;
                uint32_t rowoff1 = (uint32_t)p1 * 128;
                int sw0 = p0 & 7, sw1 = p1 & 7;

#pragma unroll
                for (int ks = 0; ks < 4; ++ks) {
                    int kc0 = ks * 2;
                    uint32_t af[4][4], bhf[2][4], blf[2][4];
#pragma unroll
                    for (int tm = 0; tm < 4; ++tm) {
                        int row = wm * 64 + tm * 16 + lr + ((lg & 1) << 3);
                        int ch = kc0 + (lg >> 1);
                        ldsm_x4(af[tm], stA + row * 128 + ((ch ^ (row & 7)) << 4));
                    }
                    {
                        int ch = kc0 + (lg & 1);
                        uint32_t o0 = rowoff0 + (uint32_t)((ch ^ sw0) << 4);
                        uint32_t o1 = rowoff1 + (uint32_t)((ch ^ sw1) << 4);
                        ldsm_x4(bhf[0], stB + o0);
                        ldsm_x4(bhf[1], stB + o1);
                        if (blo) {
                            ldsm_x4(blf[0], stBl + o0);
                            ldsm_x4(blf[1], stBl + o1);
                        }
                    }
#pragma unroll
                    for (int tm = 0; tm < 4; ++tm)
#pragma unroll
                        for (int tn = 0; tn < 4; ++tn)
                            mma16816(acc[tm][tn], af[tm], &bhf[tn >> 1][(tn & 1) * 2]);
                    if (blo) {
#pragma unroll
                        for (int tm = 0; tm < 4; ++tm)
#pragma unroll
                            for (int tn = 0; tn < 4; ++tn)
                                mma16816(acc[tm][tn], af[tm], &blf[tn >> 1][(tn & 1) * 2]);
                    }
                    if (nprod == 3) {
#pragma unroll
                        for (int tm = 0; tm < 4; ++tm) {
                            int row = wm * 64 + tm * 16 + lr + ((lg & 1) << 3);
                            int ch = kc0 + (lg >> 1);
                            ldsm_x4(af[tm], stAl + row * 128 + ((ch ^ (row & 7)) << 4));
                        }
#pragma unroll
                        for (int tm = 0; tm < 4; ++tm)
#pragma unroll
                            for (int tn = 0; tn < 4; ++tn)
                                mma16816(acc[tm][tn], af[tm], &bhf[tn >> 1][(tn & 1) * 2]);
                    }
                }
            }

            if (!last) CP_WAIT0();
            __syncthreads();
            as ^= 1;
        }
        bs ^= 1;
    }

    // ---------- epilogue ----------
#pragma unroll
    for (int tm = 0; tm < 4; ++tm) {
#pragma unroll
        for (int tn = 0; tn < 4; ++tn) {
#pragma unroll
            for (int j = 0; j < 4; ++j) {
                int m = wm * 64 + tm * 16 + (lane >> 2) + ((j >> 1) << 3);
                int n = wn * 32 + tn * 8 + ((lane & 3) << 1) + (j & 1);
                int o = coBase + m;
                int ry = n >> 6, x = n & 63;
                int y = y0 + ry;
                size_t pidx = (size_t)((y + 1) * PSTR + x + 1) * 512 + o;
                float v = acc[tm][tn][j];
                if (PRE) {
                    if (emode == 4) {
                        __half hh = __float2half_rn(v);
                        g_V116[0][pidx] = hh;
                        g_V116[1][pidx] = __float2half_rn(v - __half2float(hh));
                    } else {
                        g_A[outsel][pidx] = v;
                    }
                } else {
                    int yt = (y == 0) ? 0 : ((y == 63) ? 2 : 1);
                    int xt = (x == 0) ? 0 : ((x == 63) ? 2 : 1);
                    int cls = yt * 3 + xt;
                    if (emode == 1) {
                        float r = sigm(v + g_A[0][pidx] + g_bmap[0][node][cls * CH + o]);
                        float hval = __half2float(inH[pidx]) + __half2float(inL[pidx]);
                        atomicAdd(&g_rh[node][pidx], r * hval);
                    } else if (emode == 2) {
                        g_z[node][pidx] = sigm(v + g_A[1][pidx] + g_bmap[1][node][cls * CH + o]);
                    } else {
                        float ri = tanhf(v + g_A[2][pidx] + g_bmap[2][node][cls * CH + o]);
                        float zz = g_z[node][pidx];
                        float cs = __half2float(g_cs16[node][0][pidx]) +
                                   __half2float(g_cs16[node][1][pidx]);
                        float hv = (1.0f - zz) * ri + zz * cs;
                        __half hh = __float2half_rn(hv);
                        g_h16[node][0][pidx] = hh;
                        g_h16[node][1][pidx] = __float2half_rn(hv - __half2float(hh));
                    }
                }
            }
        }
    }
}

// ======================= ch_sum (fp16 hi/lo) + zero rh =======================
__global__ void k_chsum(int round) {
    int n = blockIdx.y;
    if (g_level[n] != round || g_nchild[n] == 0) return;
    int nc = g_nchild[n];
    size_t base = (size_t)blockIdx.x * 8192 + threadIdx.x;
#pragma unroll
    for (int e = 0; e < 32; ++e) {
        size_t i = base + (size_t)e * 256;
        if (i < BUFSZ) {
            float s = 0.0f;
            for (int ci = 0; ci < nc; ++ci) {
                int c = g_child[n][ci];
                s += __half2float(g_h16[c][0][i]) + __half2float(g_h16[c][1][i]);
            }
            __half hh = __float2half_rn(s);
            g_cs16[n][0][i] = hh;
            g_cs16[n][1][i] = __float2half_rn(s - __half2float(hh));
            g_rh[n][i] = 0.0f;
        }
    }
}

// ======================= rh -> fp16 hi (per round, active nodes) =======================
__global__ void k_cvtrh(int round) {
    int n = blockIdx.y;
    if (g_level[n] != round || g_nchild[n] == 0) return;
    size_t base = (size_t)blockIdx.x * 8192 + threadIdx.x;
#pragma unroll
    for (int e = 0; e < 32; ++e) {
        size_t i = base + (size_t)e * 256;
        if (i < BUFSZ) g_rh16[n][0][i] = __float2half_rn(g_rh[n][i]);
    }
}

// ======================= leaves =======================
__global__ void k_leaf() {
    int n = blockIdx.y;
    if (g_nchild[n] != 0) return;
    size_t base = (size_t)blockIdx.x * 8192 + threadIdx.x;
#pragma unroll
    for (int e = 0; e < 32; ++e) {
        size_t i = base + (size_t)e * 256;
        if (i < BUFSZ) {
            int c = (int)(i & 511);
            int pp = (int)(i >> 9);
            int y = pp / PSTR - 1, x = pp % PSTR - 1;
            float hv = 0.0f;
            if ((unsigned)y < 64u && (unsigned)x < 64u) {
                int yt = (y == 0) ? 0 : ((y == 63) ? 2 : 1);
                int xt = (x == 0) ? 0 : ((x == 63) ? 2 : 1);
                int cls = yt * 3 + xt;
                float zu = sigm(g_A[1][i] + g_bmap[1][n][cls * CH + c]);
                float ro = tanhf(g_A[2][i] + g_bmap[2][n][cls * CH + c]);
                hv = (1.0f - zu) * ro;
            }
            __half hh = __float2half_rn(hv);
            g_h16[n][0][i] = hh;
            g_h16[n][1][i] = __float2half_rn(hv - __half2float(hh));
        }
    }
}

// ======================= output: padded NHWC fp16 hi/lo -> NCHW fp32 =======================
__global__ __launch_bounds__(256) void k_copyout(float* out) {
    __shared__ float sm[64][129];
    int root = g_root;
    int y = blockIdx.x; int oc = blockIdx.y;
    const __half* srcH = g_h16[root][0] + (size_t)((y + 1) * PSTR + 1) * 512 + oc * 128;
    const __half* srcL = g_h16[root][1] + (size_t)((y + 1) * PSTR + 1) * 512 + oc * 128;
    for (int i = threadIdx.x; i < 64 * 128; i += 256) {
        int x = i >> 7, o = i & 127;
        sm[x][o] = __half2float(srcH[(size_t)x * 512 + o]) +
                   __half2float(srcL[(size_t)x * 512 + o]);
    }
    __syncthreads();
    for (int i = threadIdx.x; i < 64 * 128; i += 256) {
        int o = i >> 6, x = i & 63;
        out[(size_t)(oc * 128 + o) * 4096 + y * 64 + x] = sm[x][o];
    }
}

// ======================= launch =======================
extern "C" void kernel_launch(void* const* d_in, const int* in_sizes, int n_in,
                              void* d_out, int out_size) {
    const float* vis  = (const float*)d_in[0];
    const float* lang = (const float*)d_in[1];
    const int*   adj  = (const int*)d_in[2];
    const float* mw   = (const float*)d_in[3];
    const float* mb   = (const float*)d_in[4];
    const float* rw   = (const float*)d_in[5];
    const float* rb   = (const float*)d_in[6];
    const float* uw   = (const float*)d_in[7];
    const float* ub   = (const float*)d_in[8];
    const float* ow   = (const float*)d_in[9];
    const float* ob   = (const float*)d_in[10];
    float* out = (float*)d_out;

    cudaFuncSetAttribute(k_conv<1>, cudaFuncAttributeMaxDynamicSharedMemorySize, CONV_SMEM_PRE);
    cudaFuncSetAttribute(k_conv<0>, cudaFuncAttributeMaxDynamicSharedMemorySize, CONV_SMEM_REC);

    k_prep<<<1, 1>>>(adj);
    k_zero<<<dim3(520, 124), 256>>>();
    k_tvis<<<dim3(64, 4), 256>>>(vis);
    {
        size_t tot = (size_t)6 * 9 * 512 * 512 + (size_t)512 * 512;
        k_packtc<<<(unsigned)((tot + 255) / 256), 256>>>(rw, uw, ow, mw);
    }
    k_wsum<<<(3 * CH * CH) / 256, 256>>>(rw, uw, ow);
    k_lb<<<NNODE, CH>>>(lang, mw, mb);
    k_bmap<<<dim3(2, 27), 256>>>(rb, ub, ob);

    k_conv<1><<<dim3(32, 4, 1), 256, CONV_SMEM_PRE>>>(4, 0);   // V1 (3-product)
    k_conv<1><<<dim3(32, 4, 3), 256, CONV_SMEM_PRE>>>(0, 0);   // A fields (2-product)
    k_leaf<<<dim3(273, NNODE), 256>>>();

    for (int t = 1; t <= MAXROUND; ++t) {
        k_chsum<<<dim3(273, NNODE), 256>>>(t);
        k_conv<0><<<dim3(32, 4, 2 * NNODE), 256, CONV_SMEM_REC>>>(12, t);  // reset + update
        k_cvtrh<<<dim3(273, NNODE), 256>>>(t);
        k_conv<0><<<dim3(32, 4, NNODE), 256, CONV_SMEM_REC>>>(3, t);       // output
    }
    k_copyout<<<dim3(64, 4), 256>>>(out);
}